// round 11
// baseline (speedup 1.0000x reference)
#include <cuda_runtime.h>
#include <cuda_fp16.h>
#include <cstdint>
#include <cstddef>

#define BB   32
#define PS   1536
#define TNS  2048
#define NJ   128
#define QK   384
#define NC   200
#define NCT  12          // c-tiles per batch in GEMM1

// ---------------------------------------------------------------------------
// scratch (static device globals; no allocation)
// ---------------------------------------------------------------------------
__device__ __half g_w0hi[(size_t)NJ * TNS];
__device__ __half g_w0lo[(size_t)NJ * TNS];
__device__ __half g_c1hi[(size_t)PS * PS];
__device__ __half g_c1lo[(size_t)PS * PS];
__device__ __half g_h1  [(size_t)BB * NJ * PS];   // hs1^T [b][j][c], fp16
__device__ __half g_a1hi[(size_t)BB * NJ * NJ];   // A1^T  [b][k][j]
__device__ __half g_a1lo[(size_t)BB * NJ * NJ];
__device__ float g_qp  [(size_t)BB * NCT * NJ];   // q1 partials per c-tile
__device__ float g_kp  [(size_t)BB * NCT * NJ];
__device__ float g_sbc [(size_t)BB * PS];
__device__ float g_ssbc[(size_t)BB * PS];
__device__ float g_dotb[(size_t)BB * PS];
__device__ float g_wqm[PS];
__device__ float g_wkm[PS];
__device__ float g_bqkm[2];
__device__ float g_hs4[BB * PS];

// ---------------------------------------------------------------------------
// helpers
// ---------------------------------------------------------------------------
__device__ __forceinline__ uint32_t smem_u32(const void* p) {
    uint32_t a;
    asm("{ .reg .u64 t; cvta.to.shared.u64 t, %1; cvt.u32.u64 %0, t; }" : "=r"(a) : "l"(p));
    return a;
}
#define CP_COMMIT() asm volatile("cp.async.commit_group;" ::: "memory")
#define CP_WAIT0()  asm volatile("cp.async.wait_group 0;" ::: "memory")
#define CP_WAIT1()  asm volatile("cp.async.wait_group 1;" ::: "memory")

__device__ __forceinline__ void ld4(uint32_t* r, uint32_t a) {
    asm volatile("ldmatrix.sync.aligned.m8n8.x4.shared.b16 {%0,%1,%2,%3}, [%4];"
        : "=r"(r[0]), "=r"(r[1]), "=r"(r[2]), "=r"(r[3]) : "r"(a));
}
__device__ __forceinline__ void mma16816(float* d, const uint32_t* a, const uint32_t* b) {
    asm volatile(
        "mma.sync.aligned.m16n8k16.row.col.f32.f16.f16.f32 "
        "{%0,%1,%2,%3}, {%4,%5,%6,%7}, {%8,%9}, {%0,%1,%2,%3};"
        : "+f"(d[0]), "+f"(d[1]), "+f"(d[2]), "+f"(d[3])
        : "r"(a[0]), "r"(a[1]), "r"(a[2]), "r"(a[3]), "r"(b[0]), "r"(b[1]));
}

// fp32 -> (hi, lo) fp16 split: one launch covers w0 then c1
#define W0_N4  ((long)NJ * TNS / 4)     // 65536 -> 256 blocks
#define C1_N4  ((long)PS * PS / 4)      // 589824 -> 2304 blocks
__global__ void k_cvt2(const float* __restrict__ w0, const float* __restrict__ c1) {
    long i = (long)blockIdx.x * blockDim.x + threadIdx.x;
    const float* s; __half *hi, *lo;
    if (i < W0_N4) { s = w0; hi = g_w0hi; lo = g_w0lo; }
    else           { s = c1; hi = g_c1hi; lo = g_c1lo; i -= W0_N4; }
    float4 v = ((const float4*)s)[i];
    __half h0 = __float2half_rn(v.x), h1 = __float2half_rn(v.y);
    __half h2 = __float2half_rn(v.z), h3 = __float2half_rn(v.w);
    __half l0 = __float2half_rn(v.x - __half2float(h0));
    __half l1 = __float2half_rn(v.y - __half2float(h1));
    __half l2 = __float2half_rn(v.z - __half2float(h2));
    __half l3 = __float2half_rn(v.w - __half2float(h3));
    __half2 ph0; ph0.x = h0; ph0.y = h1;
    __half2 ph1; ph1.x = h2; ph1.y = h3;
    __half2 pl0; pl0.x = l0; pl0.y = l1;
    __half2 pl1; pl1.x = l2; pl1.y = l3;
    ((__half2*)hi)[i * 2 + 0] = ph0;
    ((__half2*)hi)[i * 2 + 1] = ph1;
    ((__half2*)lo)[i * 2 + 0] = pl0;
    ((__half2*)lo)[i * 2 + 1] = pl1;
}

// ---------------------------------------------------------------------------
// SMEM tile layout: 2 stages x 3 tiles, 128 rows x 64 k (fp16, 128B/row + 16 pad)
// ---------------------------------------------------------------------------
#define BK    64
#define RSTR  144
#define TILEB (128 * RSTR)     // 18432
#define STG3  (3 * TILEB)      // 55296

__device__ __forceinline__ void load_tile(uint32_t sb, const __half* g, int gstride, int k0) {
    const int t = threadIdx.x;
#pragma unroll
    for (int p = 0; p < 4; p++) {
        int idx = p * 256 + t;
        int row = idx >> 3, ch = idx & 7;
        uint32_t dst = sb + row * RSTR + ch * 16;
        const void* src = g + (size_t)row * gstride + k0 + ch * 8;
        asm volatile("cp.async.cg.shared.global [%0], [%1], 16;" :: "r"(dst), "l"(src));
    }
}

// 2-term MMA over one stage (4 k16 steps), split-A: tile0=Ah, tile1=Al, tile2=B
#define MMA_STAGE_SA(st)                                                         \
    do {                                                                         \
        _Pragma("unroll")                                                        \
        for (int ks = 0; ks < 4; ks++) {                                         \
            const uint32_t klo = ks * 32;                                        \
            uint32_t ah[4][4], bf[2][4];                                         \
            _Pragma("unroll")                                                    \
            for (int mt = 0; mt < 4; mt++) ld4(ah[mt], (st) + 0 * TILEB + aoff[mt] + klo); \
            _Pragma("unroll")                                                    \
            for (int np = 0; np < 2; np++) ld4(bf[np], (st) + 2 * TILEB + boff[np] + klo); \
            _Pragma("unroll")                                                    \
            for (int mt = 0; mt < 4; mt++)                                       \
                _Pragma("unroll")                                                \
                for (int nt = 0; nt < 4; nt++)                                   \
                    mma16816(d[mt][nt], ah[mt], &bf[nt >> 1][(nt & 1) * 2]);     \
            {                                                                    \
                uint32_t al[4][4];                                               \
                _Pragma("unroll")                                                \
                for (int mt = 0; mt < 4; mt++) ld4(al[mt], (st) + 1 * TILEB + aoff[mt] + klo); \
                _Pragma("unroll")                                                \
                for (int mt = 0; mt < 4; mt++)                                   \
                    _Pragma("unroll")                                            \
                    for (int nt = 0; nt < 4; nt++)                               \
                        mma16816(d[mt][nt], al[mt], &bf[nt >> 1][(nt & 1) * 2]); \
            }                                                                    \
        }                                                                        \
    } while (0)

// 2-term MMA over one 64-k chunk, explicit slots: A single, B hi/lo
#define MMA_STAGE_SB3(sA, sBh, sBl)                                              \
    do {                                                                         \
        _Pragma("unroll")                                                        \
        for (int ks = 0; ks < 4; ks++) {                                         \
            const uint32_t klo = ks * 32;                                        \
            uint32_t af[4][4], bh[2][4];                                         \
            _Pragma("unroll")                                                    \
            for (int mt = 0; mt < 4; mt++) ld4(af[mt], (sA) + aoff[mt] + klo);   \
            _Pragma("unroll")                                                    \
            for (int np = 0; np < 2; np++) ld4(bh[np], (sBh) + boff[np] + klo);  \
            _Pragma("unroll")                                                    \
            for (int mt = 0; mt < 4; mt++)                                       \
                _Pragma("unroll")                                                \
                for (int nt = 0; nt < 4; nt++)                                   \
                    mma16816(d[mt][nt], af[mt], &bh[nt >> 1][(nt & 1) * 2]);     \
            {                                                                    \
                uint32_t bl[2][4];                                               \
                _Pragma("unroll")                                                \
                for (int np = 0; np < 2; np++) ld4(bl[np], (sBl) + boff[np] + klo); \
                _Pragma("unroll")                                                \
                for (int mt = 0; mt < 4; mt++)                                   \
                    _Pragma("unroll")                                            \
                    for (int nt = 0; nt < 4; nt++)                               \
                        mma16816(d[mt][nt], af[mt], &bl[nt >> 1][(nt & 1) * 2]); \
            }                                                                    \
        }                                                                        \
    } while (0)

// ---------------------------------------------------------------------------
// GEMM1: hs1^T[j, c-tile] = (w0h + w0l)[j,:] . x_fp16[b, c,:]  + fused q/k partials
// ---------------------------------------------------------------------------
__device__ __forceinline__ void ldgB(float4* br, const float* pB, int K, int k0) {
    const int t = threadIdx.x;
#pragma unroll
    for (int p = 0; p < 8; p++) {
        int idx = p * 256 + t;
        int row = idx >> 4, f4 = idx & 15;
        br[p] = *(const float4*)(pB + (size_t)row * K + k0 + f4 * 4);
    }
}
__device__ __forceinline__ void cvt_sts(const float4* br, uint32_t st) {
    const int t = threadIdx.x;
#pragma unroll
    for (int p = 0; p < 8; p++) {
        int idx = p * 256 + t;
        int row = idx >> 4, f4 = idx & 15;
        float4 v = br[p];
        __half2 h01 = __floats2half2_rn(v.x, v.y);
        __half2 h23 = __floats2half2_rn(v.z, v.w);
        uint32_t off = (uint32_t)(row * RSTR + f4 * 8);
        asm volatile("st.shared.v2.b32 [%0], {%1,%2};"
            :: "r"(st + 2 * TILEB + off), "r"(*(uint32_t*)&h01), "r"(*(uint32_t*)&h23));
    }
}

__global__ __launch_bounds__(256, 1) void mma_gemm_x(
    const __half* __restrict__ Ah, const __half* __restrict__ Al,
    const float* __restrict__ Bf, long b_bstr,
    int K,
    const float* __restrict__ bias,
    __half* __restrict__ oh,
    long o_bstr, int o_rstr)
{
    extern __shared__ char dsm[];
    const uint32_t sb = smem_u32(dsm);

    const int tid = threadIdx.x;
    const int wid = tid >> 5, lane = tid & 31;
    const int bz = blockIdx.z;
    const int Boff = blockIdx.x * 128;
    const float* pBf = Bf + (size_t)bz * b_bstr + (size_t)Boff * K;

    const int m_base = (wid >> 2) * 64;
    const int n_base = (wid & 3) * 32;
    const int quad = lane >> 3, id8 = lane & 7;

    uint32_t aoff[4], boff[2];
#pragma unroll
    for (int mt = 0; mt < 4; mt++)
        aoff[mt] = (uint32_t)((m_base + mt * 16 + (quad & 1) * 8 + id8) * RSTR + ((quad >> 1) * 8) * 2);
#pragma unroll
    for (int np = 0; np < 2; np++)
        boff[np] = (uint32_t)((n_base + np * 16 + (quad >> 1) * 8 + id8) * RSTR + ((quad & 1) * 8) * 2);

    float d[4][4][4];
#pragma unroll
    for (int mt = 0; mt < 4; mt++)
#pragma unroll
        for (int nt = 0; nt < 4; nt++)
#pragma unroll
            for (int k = 0; k < 4; k++) d[mt][nt][k] = 0.f;

    const int nk = K / BK;
    float4 breg[8];

    // prologue: chunk0 + chunk1 staged
    ldgB(breg, pBf, K, 0);
    cvt_sts(breg, sb);
    load_tile(sb + 0 * TILEB, Ah, K, 0);
    load_tile(sb + 1 * TILEB, Al, K, 0);
    CP_COMMIT();
    ldgB(breg, pBf, K, BK);
    cvt_sts(breg, sb + STG3);
    load_tile(sb + STG3 + 0 * TILEB, Ah, K, BK);
    load_tile(sb + STG3 + 1 * TILEB, Al, K, BK);
    CP_COMMIT();
    CP_WAIT1();
    __syncthreads();

    for (int i = 0; i < nk; i++) {
        const uint32_t st = sb + (i & 1) * STG3;
        if (i + 2 < nk) ldgB(breg, pBf, K, (i + 2) * BK);

        MMA_STAGE_SA(st);

        __syncthreads();                      // stage (i&1) free
        if (i + 2 < nk) {
            cvt_sts(breg, st);
            load_tile(st + 0 * TILEB, Ah, K, (i + 2) * BK);
            load_tile(st + 1 * TILEB, Al, K, (i + 2) * BK);
            CP_COMMIT();
        }
        if (i + 1 < nk) {
            if (i + 2 < nk) CP_WAIT1(); else CP_WAIT0();
            __syncthreads();                  // stage (i+1) ready
        }
    }

    // epilogue: write fp16 hs1^T AND fused q/k partial sums over this c-tile
    __syncthreads();                          // smem free for reduction reuse
    float* red = (float*)dsm;                 // [2][4][128]
    const int g = lane >> 2, t2 = (lane & 3) * 2;
    const int nw = wid & 3;
#pragma unroll
    for (int mt = 0; mt < 4; mt++) {
        const int r0 = m_base + mt * 16 + g;
        const int r1 = r0 + 8;
        const float bv0 = bias[r0];
        const float bv1 = bias[r1];
        const size_t base0 = (size_t)bz * o_bstr + (size_t)r0 * o_rstr + Boff;
        const size_t base1 = (size_t)bz * o_bstr + (size_t)r1 * o_rstr + Boff;
        float pq0 = 0.f, pk0 = 0.f, pq1 = 0.f, pk1 = 0.f;
#pragma unroll
        for (int nt = 0; nt < 4; nt++) {
            const int col = n_base + nt * 8 + t2;
            float v00 = d[mt][nt][0] + bv0, v01 = d[mt][nt][1] + bv0;
            float v10 = d[mt][nt][2] + bv1, v11 = d[mt][nt][3] + bv1;
            *(__half2*)(oh + base0 + col) = __floats2half2_rn(v00, v01);
            *(__half2*)(oh + base1 + col) = __floats2half2_rn(v10, v11);
            float wqa = g_wqm[Boff + col], wqb = g_wqm[Boff + col + 1];
            float wka = g_wkm[Boff + col], wkb = g_wkm[Boff + col + 1];
            pq0 = fmaf(v00, wqa, fmaf(v01, wqb, pq0));
            pk0 = fmaf(v00, wka, fmaf(v01, wkb, pk0));
            pq1 = fmaf(v10, wqa, fmaf(v11, wqb, pq1));
            pk1 = fmaf(v10, wka, fmaf(v11, wkb, pk1));
        }
#pragma unroll
        for (int o = 2; o > 0; o >>= 1) {
            pq0 += __shfl_down_sync(0xffffffffu, pq0, o, 4);
            pk0 += __shfl_down_sync(0xffffffffu, pk0, o, 4);
            pq1 += __shfl_down_sync(0xffffffffu, pq1, o, 4);
            pk1 += __shfl_down_sync(0xffffffffu, pk1, o, 4);
        }
        if ((lane & 3) == 0) {
            red[0 * 512 + nw * 128 + r0] = pq0; red[0 * 512 + nw * 128 + r1] = pq1;
            red[1 * 512 + nw * 128 + r0] = pk0; red[1 * 512 + nw * 128 + r1] = pk1;
        }
    }
    __syncthreads();
    if (tid < 128) {
        float q = red[tid] + red[128 + tid] + red[256 + tid] + red[384 + tid];
        float k = red[512 + tid] + red[640 + tid] + red[768 + tid] + red[896 + tid];
        const size_t o = ((size_t)bz * NCT + blockIdx.x) * NJ + tid;
        g_qp[o] = q;
        g_kp[o] = k;
    }
}

// ---------------------------------------------------------------------------
// q1/k1 from partials + A1^T hi/lo, one block per batch
// ---------------------------------------------------------------------------
__global__ void k_qkA1(const float* __restrict__ adj, const float* __restrict__ alpha) {
    __shared__ float q1s[NJ], k1s[NJ];
    const int b = blockIdx.x, tid = threadIdx.x;
    if (tid < 128) {
        float q = g_bqkm[0], k = g_bqkm[1];
#pragma unroll
        for (int t = 0; t < NCT; t++) {
            q += g_qp[((size_t)b * NCT + t) * NJ + tid];
            k += g_kp[((size_t)b * NCT + t) * NJ + tid];
        }
        q1s[tid] = q; k1s[tid] = k;
    }
    __syncthreads();
    const float a = alpha[0];
#pragma unroll
    for (int u = 0; u < 64; u++) {
        const int idx = u * 256 + tid;       // 0..16383
        const int k = idx >> 7, j = idx & 127;
        float v = adj[j * NJ + k] + tanhf(q1s[j] - k1s[k]) * a;
        __half h = __float2half_rn(v);
        __half l = __float2half_rn(v - __half2float(h));
        g_a1hi[(size_t)b * NJ * NJ + idx] = h;
        g_a1lo[(size_t)b * NJ * NJ + idx] = l;
    }
}

// ---------------------------------------------------------------------------
// GEMM2 + fused GEMM3 + fused BN-stat/pool (unchanged from R10)
// ---------------------------------------------------------------------------
__global__ __launch_bounds__(256, 1) void mma_gemm2f(
    const __half* __restrict__ C1h, const __half* __restrict__ C1l,
    const __half* __restrict__ H1, long h1_bstr,
    const __half* __restrict__ A1h, const __half* __restrict__ A1l,
    int K,
    const float* __restrict__ bias,
    const float* __restrict__ w1f,
    float* __restrict__ sbc, float* __restrict__ ssbc, float* __restrict__ dotb)
{
    extern __shared__ char dsm[];
    const uint32_t sb = smem_u32(dsm);

    const int tid = threadIdx.x;
    const int wid = tid >> 5, lane = tid & 31;
    const int bz = blockIdx.z;
    const int Aoff = blockIdx.x * 128;

    const __half* p0 = C1h + (size_t)Aoff * K;
    const __half* p1 = C1l + (size_t)Aoff * K;
    const __half* p2 = H1 + (size_t)bz * h1_bstr;
    const __half* a1h_b = A1h + (size_t)bz * NJ * NJ;
    const __half* a1l_b = A1l + (size_t)bz * NJ * NJ;

    const int m_base = (wid >> 2) * 64;
    const int n_base = (wid & 3) * 32;
    const int quad = lane >> 3, id8 = lane & 7;

    uint32_t aoff[4], boff[2];
#pragma unroll
    for (int mt = 0; mt < 4; mt++)
        aoff[mt] = (uint32_t)((m_base + mt * 16 + (quad & 1) * 8 + id8) * RSTR + ((quad >> 1) * 8) * 2);
#pragma unroll
    for (int np = 0; np < 2; np++)
        boff[np] = (uint32_t)((n_base + np * 16 + (quad >> 1) * 8 + id8) * RSTR + ((quad & 1) * 8) * 2);

    float d[4][4][4];
#pragma unroll
    for (int mt = 0; mt < 4; mt++)
#pragma unroll
        for (int nt = 0; nt < 4; nt++)
#pragma unroll
            for (int k = 0; k < 4; k++) d[mt][nt][k] = 0.f;

    const int nk = K / BK;

    load_tile(sb + 0 * TILEB, p0, K, 0);
    load_tile(sb + 1 * TILEB, p1, K, 0);
    load_tile(sb + 2 * TILEB, p2, K, 0);
    CP_COMMIT();
    load_tile(sb + STG3 + 0 * TILEB, p0, K, BK);
    load_tile(sb + STG3 + 1 * TILEB, p1, K, BK);
    load_tile(sb + STG3 + 2 * TILEB, p2, K, BK);
    CP_COMMIT();

    for (int i = 0; i < nk; i++) {
        if (i + 1 < nk) CP_WAIT1(); else CP_WAIT0();
        __syncthreads();
        const uint32_t st = sb + (i & 1) * STG3;

        MMA_STAGE_SA(st);

        __syncthreads();
        if (i + 2 < nk) {
            const uint32_t nstg = sb + (i & 1) * STG3;
            const int k0 = (i + 2) * BK;
            load_tile(nstg + 0 * TILEB, p0, K, k0);
            load_tile(nstg + 1 * TILEB, p1, K, k0);
            load_tile(nstg + 2 * TILEB, p2, K, k0);
            CP_COMMIT();
        }
    }

    // --- fused GEMM3: preload A1 hi/lo into free slots ---
    load_tile(sb + 2 * TILEB, a1h_b, NJ, 0);
    load_tile(sb + 3 * TILEB, a1l_b, NJ, 0);
    load_tile(sb + 4 * TILEB, a1h_b, NJ, 64);
    load_tile(sb + 5 * TILEB, a1l_b, NJ, 64);
    CP_COMMIT();

    // write hs2 tile (+bias, fp16) into A slots, j split across 2 slots
    const int g = lane >> 2, t2 = (lane & 3) * 2;
#pragma unroll
    for (int mt = 0; mt < 4; mt++) {
        const int r0 = m_base + mt * 16 + g;
        const int r1 = r0 + 8;
        const float bv0 = bias[Aoff + r0];
        const float bv1 = bias[Aoff + r1];
#pragma unroll
        for (int nt = 0; nt < 4; nt++) {
            const int col = n_base + nt * 8 + t2;
            const uint32_t cslot = (uint32_t)(col >> 6) * TILEB;
            const uint32_t cl = (uint32_t)(col & 63) * 2;
            __half2 v0 = __floats2half2_rn(d[mt][nt][0] + bv0, d[mt][nt][1] + bv0);
            __half2 v1 = __floats2half2_rn(d[mt][nt][2] + bv1, d[mt][nt][3] + bv1);
            asm volatile("st.shared.b32 [%0], %1;"
                :: "r"(sb + cslot + (uint32_t)r0 * RSTR + cl), "r"(*(uint32_t*)&v0));
            asm volatile("st.shared.b32 [%0], %1;"
                :: "r"(sb + cslot + (uint32_t)r1 * RSTR + cl), "r"(*(uint32_t*)&v1));
        }
    }
    CP_WAIT0();
    __syncthreads();

#pragma unroll
    for (int mt = 0; mt < 4; mt++)
#pragma unroll
        for (int nt = 0; nt < 4; nt++)
#pragma unroll
            for (int k = 0; k < 4; k++) d[mt][nt][k] = 0.f;

    MMA_STAGE_SB3(sb + 0 * TILEB, sb + 2 * TILEB, sb + 3 * TILEB);
    MMA_STAGE_SB3(sb + 1 * TILEB, sb + 4 * TILEB, sb + 5 * TILEB);

    // --- fused BN-stat + pool epilogue ---
    __syncthreads();
    float* red = (float*)dsm;
    const int nw = wid & 3;
#pragma unroll
    for (int mt = 0; mt < 4; mt++) {
        float s0r = 0, ss0 = 0, dt0 = 0, s1r = 0, ss1 = 0, dt1 = 0;
#pragma unroll
        for (int nt = 0; nt < 4; nt++) {
            const int col = n_base + nt * 8 + t2;
            float wa = __ldg(w1f + col), wb = __ldg(w1f + col + 1);
            float v00 = d[mt][nt][0], v01 = d[mt][nt][1];
            float v10 = d[mt][nt][2], v11 = d[mt][nt][3];
            s0r += v00 + v01;  ss0 = fmaf(v00, v00, fmaf(v01, v01, ss0));
            dt0 = fmaf(v00, wa, fmaf(v01, wb, dt0));
            s1r += v10 + v11;  ss1 = fmaf(v10, v10, fmaf(v11, v11, ss1));
            dt1 = fmaf(v10, wa, fmaf(v11, wb, dt1));
        }
#pragma unroll
        for (int o = 2; o > 0; o >>= 1) {
            s0r += __shfl_down_sync(0xffffffffu, s0r, o, 4);
            ss0 += __shfl_down_sync(0xffffffffu, ss0, o, 4);
            dt0 += __shfl_down_sync(0xffffffffu, dt0, o, 4);
            s1r += __shfl_down_sync(0xffffffffu, s1r, o, 4);
            ss1 += __shfl_down_sync(0xffffffffu, ss1, o, 4);
            dt1 += __shfl_down_sync(0xffffffffu, dt1, o, 4);
        }
        if ((lane & 3) == 0) {
            const int r0 = m_base + mt * 16 + g, r1 = r0 + 8;
            red[0 * 512 + nw * 128 + r0] = s0r; red[0 * 512 + nw * 128 + r1] = s1r;
            red[1 * 512 + nw * 128 + r0] = ss0; red[1 * 512 + nw * 128 + r1] = ss1;
            red[2 * 512 + nw * 128 + r0] = dt0; red[2 * 512 + nw * 128 + r1] = dt1;
        }
    }
    __syncthreads();
    if (tid < 128) {
        float s  = red[tid] + red[128 + tid] + red[256 + tid] + red[384 + tid];
        float ss = red[512 + tid] + red[640 + tid] + red[768 + tid] + red[896 + tid];
        float dt = red[1024 + tid] + red[1152 + tid] + red[1280 + tid] + red[1408 + tid];
        const size_t o = (size_t)bz * PS + Aoff + tid;
        sbc[o] = s; ssbc[o] = ss; dotb[o] = dt;
    }
}

// ---------------------------------------------------------------------------
// small kernels
// ---------------------------------------------------------------------------
__global__ void k_wmeans(const float* __restrict__ wq, const float* __restrict__ wk,
                         const float* __restrict__ bq, const float* __restrict__ bk) {
    const int bx = blockIdx.x;
    if (bx < 48) {
        const int tx = threadIdx.x & 31, ty = threadIdx.x >> 5;
        const int c = bx * 32 + tx;
        float sq = 0.f, sk = 0.f;
        for (int o = ty; o < QK; o += 8) {
            sq += wq[(size_t)o * PS + c];
            sk += wk[(size_t)o * PS + c];
        }
        __shared__ float aq[8][32], ak[8][32];
        aq[ty][tx] = sq; ak[ty][tx] = sk;
        __syncthreads();
        if (ty == 0) {
#pragma unroll
            for (int u = 1; u < 8; u++) { sq += aq[u][tx]; sk += ak[u][tx]; }
            g_wqm[c] = sq * (1.0f / QK);
            g_wkm[c] = sk * (1.0f / QK);
        }
    } else if (threadIdx.x < 32) {
        const float* src = (bx == 48) ? bq : bk;
        float s = 0.f;
        for (int o = threadIdx.x; o < QK; o += 32) s += src[o];
#pragma unroll
        for (int o = 16; o > 0; o >>= 1) s += __shfl_down_sync(0xffffffffu, s, o);
        if (threadIdx.x == 0) g_bqkm[bx - 48] = s * (1.0f / QK);
    }
}

__global__ void k_hs4(const float* __restrict__ gamma, const float* __restrict__ beta,
                      const float* __restrict__ w1, const float* __restrict__ b1) {
    const int c = blockIdx.x * 256 + threadIdx.x;
    float sw = 0.f;
#pragma unroll 16
    for (int j = 0; j < NJ; j++) sw += w1[j];
    float s = 0.f, ss = 0.f;
    for (int b = 0; b < BB; b++) {
        s  += g_sbc [b * PS + c];
        ss += g_ssbc[b * PS + c];
    }
    const float inv = 1.0f / (BB * NJ);
    float mean = s * inv;
    float var = ss * inv - mean * mean;
    float rstd = rsqrtf(var + 1e-5f);
    float ga = gamma[c] * rstd;
    float be = beta[c] * sw + b1[0];
    float msw = mean * sw;
    for (int b = 0; b < BB; b++)
        g_hs4[b * PS + c] = ga * (g_dotb[b * PS + c] - msw) + be;
}

__global__ void k_cls(const float* __restrict__ wcls, const float* __restrict__ bcls,
                      float* __restrict__ out) {
    __shared__ __align__(16) float sh[PS];
    const int b = blockIdx.x;
    for (int i = threadIdx.x; i < PS; i += blockDim.x) sh[i] = g_hs4[b * PS + i];
    __syncthreads();
    const int n = threadIdx.x;
    if (n < NC) {
        float acc = bcls[n];
        const float4* w4 = (const float4*)(wcls + (size_t)n * PS);
        const float4* s4 = (const float4*)sh;
        for (int c = 0; c < PS / 4; c++) {
            float4 w = w4[c], s = s4[c];
            acc = fmaf(s.x, w.x, acc);
            acc = fmaf(s.y, w.y, acc);
            acc = fmaf(s.z, w.z, acc);
            acc = fmaf(s.w, w.w, acc);
        }
        out[b * NC + n] = acc;
    }
}

// ---------------------------------------------------------------------------
// launch
// ---------------------------------------------------------------------------
extern "C" void kernel_launch(void* const* d_in, const int* in_sizes, int n_in,
                              void* d_out, int out_size) {
    (void)in_sizes; (void)n_in; (void)out_size;
    const float* x       = (const float*)d_in[0];
    const float* w_pool0 = (const float*)d_in[1];
    const float* b_pool0 = (const float*)d_in[2];
    const float* adj1    = (const float*)d_in[3];
    const float* w_q     = (const float*)d_in[4];
    const float* b_q     = (const float*)d_in[5];
    const float* w_k     = (const float*)d_in[6];
    const float* b_k     = (const float*)d_in[7];
    const float* alpha   = (const float*)d_in[8];
    const float* w_c1    = (const float*)d_in[9];
    const float* b_c1    = (const float*)d_in[10];
    const float* gamma   = (const float*)d_in[11];
    const float* beta    = (const float*)d_in[12];
    const float* w_pool1 = (const float*)d_in[13];
    const float* b_pool1 = (const float*)d_in[14];
    const float* w_cls   = (const float*)d_in[15];
    const float* b_cls   = (const float*)d_in[16];
    float* out = (float*)d_out;

    __half *w0hi, *w0lo, *c1hi, *c1lo, *h1, *a1hi, *a1lo;
    float *sbc, *ssbc, *dotb;
    cudaGetSymbolAddress((void**)&w0hi, g_w0hi);
    cudaGetSymbolAddress((void**)&w0lo, g_w0lo);
    cudaGetSymbolAddress((void**)&c1hi, g_c1hi);
    cudaGetSymbolAddress((void**)&c1lo, g_c1lo);
    cudaGetSymbolAddress((void**)&h1,   g_h1);
    cudaGetSymbolAddress((void**)&a1hi, g_a1hi);
    cudaGetSymbolAddress((void**)&a1lo, g_a1lo);
    cudaGetSymbolAddress((void**)&sbc,  g_sbc);
    cudaGetSymbolAddress((void**)&ssbc, g_ssbc);
    cudaGetSymbolAddress((void**)&dotb, g_dotb);

    const int smem_bytes = 2 * STG3;   // 110592
    cudaFuncSetAttribute(mma_gemm2f, cudaFuncAttributeMaxDynamicSharedMemorySize, smem_bytes);
    cudaFuncSetAttribute(mma_gemm_x, cudaFuncAttributeMaxDynamicSharedMemorySize, smem_bytes);

    // weight hi/lo splits (one launch) + q/k weight means
    k_cvt2<<<(unsigned)((W0_N4 + C1_N4) / 256), 256>>>(w_pool0, w_c1);
    k_wmeans<<<50, 256>>>(w_q, w_k, b_q, b_k);

    // GEMM1 + fused q/k partials
    mma_gemm_x<<<dim3(NCT, 1, BB), 256, smem_bytes>>>(
        w0hi, w0lo,
        x, (long)PS * TNS,
        TNS, b_pool0,
        h1, (long)NJ * PS, PS);

    // q1/k1 reduce + A1^T build (one kernel)
    k_qkA1<<<BB, 256>>>(adj1, alpha);

    // GEMM2 + fused GEMM3 + fused BN-stat/pool
    mma_gemm2f<<<dim3(NCT, 1, BB), 256, smem_bytes>>>(
        c1hi, c1lo,
        h1, (long)NJ * PS,
        a1hi, a1lo,
        PS, b_c1,
        w_pool1, sbc, ssbc, dotb);

    k_hs4<<<PS / 256, 256>>>(gamma, beta, w_pool1, b_pool1);
    k_cls<<<BB, 256>>>(w_cls, b_cls, out);
}

// round 12
// speedup vs baseline: 1.0445x; 1.0445x over previous
#include <cuda_runtime.h>
#include <cuda_fp16.h>
#include <cstdint>
#include <cstddef>

#define BB   32
#define PS   1536
#define TNS  2048
#define NJ   128
#define QK   384
#define NC   200
#define NCT  12          // c-tiles per batch in GEMM1

// ---------------------------------------------------------------------------
// scratch (static device globals; no allocation)
// ---------------------------------------------------------------------------
__device__ __half g_w0hi[(size_t)NJ * TNS];
__device__ __half g_w0lo[(size_t)NJ * TNS];
__device__ __half g_c1hi[(size_t)PS * PS];
__device__ __half g_c1lo[(size_t)PS * PS];
__device__ __half g_h1  [(size_t)BB * NJ * PS];   // hs1^T [b][j][c], fp16
__device__ __half g_a1hi[(size_t)BB * NJ * NJ];   // A1^T  [b][k][j]
__device__ __half g_a1lo[(size_t)BB * NJ * NJ];
__device__ float g_qp  [(size_t)BB * NCT * NJ];   // q1 partials per c-tile
__device__ float g_kp  [(size_t)BB * NCT * NJ];
__device__ float g_sbc [(size_t)BB * PS];
__device__ float g_ssbc[(size_t)BB * PS];
__device__ float g_dotb[(size_t)BB * PS];
__device__ float g_wqm[PS];
__device__ float g_wkm[PS];
__device__ float g_bqkm[2];
__device__ float g_hs4[BB * PS];

// ---------------------------------------------------------------------------
// helpers
// ---------------------------------------------------------------------------
__device__ __forceinline__ uint32_t smem_u32(const void* p) {
    uint32_t a;
    asm("{ .reg .u64 t; cvta.to.shared.u64 t, %1; cvt.u32.u64 %0, t; }" : "=r"(a) : "l"(p));
    return a;
}
#define CP_COMMIT() asm volatile("cp.async.commit_group;" ::: "memory")
#define CP_WAIT0()  asm volatile("cp.async.wait_group 0;" ::: "memory")
#define CP_WAIT1()  asm volatile("cp.async.wait_group 1;" ::: "memory")

__device__ __forceinline__ void ld4(uint32_t* r, uint32_t a) {
    asm volatile("ldmatrix.sync.aligned.m8n8.x4.shared.b16 {%0,%1,%2,%3}, [%4];"
        : "=r"(r[0]), "=r"(r[1]), "=r"(r[2]), "=r"(r[3]) : "r"(a));
}
__device__ __forceinline__ void mma16816(float* d, const uint32_t* a, const uint32_t* b) {
    asm volatile(
        "mma.sync.aligned.m16n8k16.row.col.f32.f16.f16.f32 "
        "{%0,%1,%2,%3}, {%4,%5,%6,%7}, {%8,%9}, {%0,%1,%2,%3};"
        : "+f"(d[0]), "+f"(d[1]), "+f"(d[2]), "+f"(d[3])
        : "r"(a[0]), "r"(a[1]), "r"(a[2]), "r"(a[3]), "r"(b[0]), "r"(b[1]));
}

// fp32 -> (hi, lo) fp16 split: one launch covers w0 then c1
#define W0_N4  ((long)NJ * TNS / 4)     // 65536 -> 256 blocks
#define C1_N4  ((long)PS * PS / 4)      // 589824 -> 2304 blocks
__global__ void k_cvt2(const float* __restrict__ w0, const float* __restrict__ c1) {
    long i = (long)blockIdx.x * blockDim.x + threadIdx.x;
    const float* s; __half *hi, *lo;
    if (i < W0_N4) { s = w0; hi = g_w0hi; lo = g_w0lo; }
    else           { s = c1; hi = g_c1hi; lo = g_c1lo; i -= W0_N4; }
    float4 v = ((const float4*)s)[i];
    __half h0 = __float2half_rn(v.x), h1 = __float2half_rn(v.y);
    __half h2 = __float2half_rn(v.z), h3 = __float2half_rn(v.w);
    __half l0 = __float2half_rn(v.x - __half2float(h0));
    __half l1 = __float2half_rn(v.y - __half2float(h1));
    __half l2 = __float2half_rn(v.z - __half2float(h2));
    __half l3 = __float2half_rn(v.w - __half2float(h3));
    __half2 ph0; ph0.x = h0; ph0.y = h1;
    __half2 ph1; ph1.x = h2; ph1.y = h3;
    __half2 pl0; pl0.x = l0; pl0.y = l1;
    __half2 pl1; pl1.x = l2; pl1.y = l3;
    ((__half2*)hi)[i * 2 + 0] = ph0;
    ((__half2*)hi)[i * 2 + 1] = ph1;
    ((__half2*)lo)[i * 2 + 0] = pl0;
    ((__half2*)lo)[i * 2 + 1] = pl1;
}

// ---------------------------------------------------------------------------
// SMEM tile layout: 2 stages x 3 tiles, 128 rows x 64 k (fp16, 128B/row + 16 pad)
// ---------------------------------------------------------------------------
#define BK    64
#define RSTR  144
#define TILEB (128 * RSTR)     // 18432
#define STG3  (3 * TILEB)      // 55296

__device__ __forceinline__ void load_tile(uint32_t sb, const __half* g, int gstride, int k0) {
    const int t = threadIdx.x;
#pragma unroll
    for (int p = 0; p < 4; p++) {
        int idx = p * 256 + t;
        int row = idx >> 3, ch = idx & 7;
        uint32_t dst = sb + row * RSTR + ch * 16;
        const void* src = g + (size_t)row * gstride + k0 + ch * 8;
        asm volatile("cp.async.cg.shared.global [%0], [%1], 16;" :: "r"(dst), "l"(src));
    }
}

// 2-term MMA over one stage (4 k16 steps), split-A: tile0=Ah, tile1=Al, tile2=B
#define MMA_STAGE_SA(st)                                                         \
    do {                                                                         \
        _Pragma("unroll")                                                        \
        for (int ks = 0; ks < 4; ks++) {                                         \
            const uint32_t klo = ks * 32;                                        \
            uint32_t ah[4][4], bf[2][4];                                         \
            _Pragma("unroll")                                                    \
            for (int mt = 0; mt < 4; mt++) ld4(ah[mt], (st) + 0 * TILEB + aoff[mt] + klo); \
            _Pragma("unroll")                                                    \
            for (int np = 0; np < 2; np++) ld4(bf[np], (st) + 2 * TILEB + boff[np] + klo); \
            _Pragma("unroll")                                                    \
            for (int mt = 0; mt < 4; mt++)                                       \
                _Pragma("unroll")                                                \
                for (int nt = 0; nt < 4; nt++)                                   \
                    mma16816(d[mt][nt], ah[mt], &bf[nt >> 1][(nt & 1) * 2]);     \
            {                                                                    \
                uint32_t al[4][4];                                               \
                _Pragma("unroll")                                                \
                for (int mt = 0; mt < 4; mt++) ld4(al[mt], (st) + 1 * TILEB + aoff[mt] + klo); \
                _Pragma("unroll")                                                \
                for (int mt = 0; mt < 4; mt++)                                   \
                    _Pragma("unroll")                                            \
                    for (int nt = 0; nt < 4; nt++)                               \
                        mma16816(d[mt][nt], al[mt], &bf[nt >> 1][(nt & 1) * 2]); \
            }                                                                    \
        }                                                                        \
    } while (0)

// 2-term MMA over one 64-k chunk, explicit slots: A single, B hi/lo
#define MMA_STAGE_SB3(sA, sBh, sBl)                                              \
    do {                                                                         \
        _Pragma("unroll")                                                        \
        for (int ks = 0; ks < 4; ks++) {                                         \
            const uint32_t klo = ks * 32;                                        \
            uint32_t af[4][4], bh[2][4];                                         \
            _Pragma("unroll")                                                    \
            for (int mt = 0; mt < 4; mt++) ld4(af[mt], (sA) + aoff[mt] + klo);   \
            _Pragma("unroll")                                                    \
            for (int np = 0; np < 2; np++) ld4(bh[np], (sBh) + boff[np] + klo);  \
            _Pragma("unroll")                                                    \
            for (int mt = 0; mt < 4; mt++)                                       \
                _Pragma("unroll")                                                \
                for (int nt = 0; nt < 4; nt++)                                   \
                    mma16816(d[mt][nt], af[mt], &bh[nt >> 1][(nt & 1) * 2]);     \
            {                                                                    \
                uint32_t bl[2][4];                                               \
                _Pragma("unroll")                                                \
                for (int np = 0; np < 2; np++) ld4(bl[np], (sBl) + boff[np] + klo); \
                _Pragma("unroll")                                                \
                for (int mt = 0; mt < 4; mt++)                                   \
                    _Pragma("unroll")                                            \
                    for (int nt = 0; nt < 4; nt++)                               \
                        mma16816(d[mt][nt], af[mt], &bl[nt >> 1][(nt & 1) * 2]); \
            }                                                                    \
        }                                                                        \
    } while (0)

// ---------------------------------------------------------------------------
// GEMM1: hs1^T[j, c-tile] = (w0h + w0l)[j,:] . x_fp16[b, c,:]  + fused q/k partials
// ---------------------------------------------------------------------------
__device__ __forceinline__ void ldgB(float4* br, const float* pB, int K, int k0) {
    const int t = threadIdx.x;
#pragma unroll
    for (int p = 0; p < 8; p++) {
        int idx = p * 256 + t;
        int row = idx >> 4, f4 = idx & 15;
        br[p] = *(const float4*)(pB + (size_t)row * K + k0 + f4 * 4);
    }
}
__device__ __forceinline__ void cvt_sts(const float4* br, uint32_t st) {
    const int t = threadIdx.x;
#pragma unroll
    for (int p = 0; p < 8; p++) {
        int idx = p * 256 + t;
        int row = idx >> 4, f4 = idx & 15;
        float4 v = br[p];
        __half2 h01 = __floats2half2_rn(v.x, v.y);
        __half2 h23 = __floats2half2_rn(v.z, v.w);
        uint32_t off = (uint32_t)(row * RSTR + f4 * 8);
        asm volatile("st.shared.v2.b32 [%0], {%1,%2};"
            :: "r"(st + 2 * TILEB + off), "r"(*(uint32_t*)&h01), "r"(*(uint32_t*)&h23));
    }
}

__global__ __launch_bounds__(256, 1) void mma_gemm_x(
    const __half* __restrict__ Ah, const __half* __restrict__ Al,
    const float* __restrict__ Bf, long b_bstr,
    int K,
    const float* __restrict__ bias,
    __half* __restrict__ oh,
    long o_bstr, int o_rstr)
{
    extern __shared__ char dsm[];
    const uint32_t sb = smem_u32(dsm);

    const int tid = threadIdx.x;
    const int wid = tid >> 5, lane = tid & 31;
    const int bz = blockIdx.z;
    const int Boff = blockIdx.x * 128;
    const float* pBf = Bf + (size_t)bz * b_bstr + (size_t)Boff * K;

    const int m_base = (wid >> 2) * 64;
    const int n_base = (wid & 3) * 32;
    const int quad = lane >> 3, id8 = lane & 7;

    uint32_t aoff[4], boff[2];
#pragma unroll
    for (int mt = 0; mt < 4; mt++)
        aoff[mt] = (uint32_t)((m_base + mt * 16 + (quad & 1) * 8 + id8) * RSTR + ((quad >> 1) * 8) * 2);
#pragma unroll
    for (int np = 0; np < 2; np++)
        boff[np] = (uint32_t)((n_base + np * 16 + (quad >> 1) * 8 + id8) * RSTR + ((quad & 1) * 8) * 2);

    float d[4][4][4];
#pragma unroll
    for (int mt = 0; mt < 4; mt++)
#pragma unroll
        for (int nt = 0; nt < 4; nt++)
#pragma unroll
            for (int k = 0; k < 4; k++) d[mt][nt][k] = 0.f;

    const int nk = K / BK;
    float4 breg[8];

    // prologue: chunk0 + chunk1 staged
    ldgB(breg, pBf, K, 0);
    cvt_sts(breg, sb);
    load_tile(sb + 0 * TILEB, Ah, K, 0);
    load_tile(sb + 1 * TILEB, Al, K, 0);
    CP_COMMIT();
    ldgB(breg, pBf, K, BK);
    cvt_sts(breg, sb + STG3);
    load_tile(sb + STG3 + 0 * TILEB, Ah, K, BK);
    load_tile(sb + STG3 + 1 * TILEB, Al, K, BK);
    CP_COMMIT();
    CP_WAIT1();
    __syncthreads();

    for (int i = 0; i < nk; i++) {
        const uint32_t st = sb + (i & 1) * STG3;
        if (i + 2 < nk) ldgB(breg, pBf, K, (i + 2) * BK);

        MMA_STAGE_SA(st);

        __syncthreads();                      // stage (i&1) free
        if (i + 2 < nk) {
            cvt_sts(breg, st);
            load_tile(st + 0 * TILEB, Ah, K, (i + 2) * BK);
            load_tile(st + 1 * TILEB, Al, K, (i + 2) * BK);
            CP_COMMIT();
        }
        if (i + 1 < nk) {
            if (i + 2 < nk) CP_WAIT1(); else CP_WAIT0();
            __syncthreads();                  // stage (i+1) ready
        }
    }

    // epilogue: write fp16 hs1^T AND fused q/k partial sums over this c-tile
    __syncthreads();                          // smem free for reduction reuse
    float* red = (float*)dsm;                 // [2][4][128]
    const int g = lane >> 2, t2 = (lane & 3) * 2;
    const int nw = wid & 3;
#pragma unroll
    for (int mt = 0; mt < 4; mt++) {
        const int r0 = m_base + mt * 16 + g;
        const int r1 = r0 + 8;
        const float bv0 = bias[r0];
        const float bv1 = bias[r1];
        const size_t base0 = (size_t)bz * o_bstr + (size_t)r0 * o_rstr + Boff;
        const size_t base1 = (size_t)bz * o_bstr + (size_t)r1 * o_rstr + Boff;
        float pq0 = 0.f, pk0 = 0.f, pq1 = 0.f, pk1 = 0.f;
#pragma unroll
        for (int nt = 0; nt < 4; nt++) {
            const int col = n_base + nt * 8 + t2;
            float v00 = d[mt][nt][0] + bv0, v01 = d[mt][nt][1] + bv0;
            float v10 = d[mt][nt][2] + bv1, v11 = d[mt][nt][3] + bv1;
            *(__half2*)(oh + base0 + col) = __floats2half2_rn(v00, v01);
            *(__half2*)(oh + base1 + col) = __floats2half2_rn(v10, v11);
            float wqa = g_wqm[Boff + col], wqb = g_wqm[Boff + col + 1];
            float wka = g_wkm[Boff + col], wkb = g_wkm[Boff + col + 1];
            pq0 = fmaf(v00, wqa, fmaf(v01, wqb, pq0));
            pk0 = fmaf(v00, wka, fmaf(v01, wkb, pk0));
            pq1 = fmaf(v10, wqa, fmaf(v11, wqb, pq1));
            pk1 = fmaf(v10, wka, fmaf(v11, wkb, pk1));
        }
#pragma unroll
        for (int o = 2; o > 0; o >>= 1) {
            pq0 += __shfl_down_sync(0xffffffffu, pq0, o, 4);
            pk0 += __shfl_down_sync(0xffffffffu, pk0, o, 4);
            pq1 += __shfl_down_sync(0xffffffffu, pq1, o, 4);
            pk1 += __shfl_down_sync(0xffffffffu, pk1, o, 4);
        }
        if ((lane & 3) == 0) {
            red[0 * 512 + nw * 128 + r0] = pq0; red[0 * 512 + nw * 128 + r1] = pq1;
            red[1 * 512 + nw * 128 + r0] = pk0; red[1 * 512 + nw * 128 + r1] = pk1;
        }
    }
    __syncthreads();
    if (tid < 128) {
        float q = red[tid] + red[128 + tid] + red[256 + tid] + red[384 + tid];
        float k = red[512 + tid] + red[640 + tid] + red[768 + tid] + red[896 + tid];
        const size_t o = ((size_t)bz * NCT + blockIdx.x) * NJ + tid;
        g_qp[o] = q;
        g_kp[o] = k;
    }
}

// ---------------------------------------------------------------------------
// q1/k1 from partials + A1^T hi/lo; grid (8, BB) -> each block does 2048 elems
// ---------------------------------------------------------------------------
__global__ void k_qkA1(const float* __restrict__ adj, const float* __restrict__ alpha) {
    __shared__ float q1s[NJ], k1s[NJ];
    const int b = blockIdx.y, tid = threadIdx.x;
    if (tid < 128) {
        float q = g_bqkm[0], k = g_bqkm[1];
#pragma unroll
        for (int t = 0; t < NCT; t++) {
            q += g_qp[((size_t)b * NCT + t) * NJ + tid];
            k += g_kp[((size_t)b * NCT + t) * NJ + tid];
        }
        q1s[tid] = q; k1s[tid] = k;
    }
    __syncthreads();
    const float a = alpha[0];
    const int base = blockIdx.x * 2048;
#pragma unroll
    for (int u = 0; u < 8; u++) {
        const int idx = base + u * 256 + tid;       // 0..16383
        const int k = idx >> 7, j = idx & 127;
        float v = adj[j * NJ + k] + tanhf(q1s[j] - k1s[k]) * a;
        __half h = __float2half_rn(v);
        __half l = __float2half_rn(v - __half2float(h));
        g_a1hi[(size_t)b * NJ * NJ + idx] = h;
        g_a1lo[(size_t)b * NJ * NJ + idx] = l;
    }
}

// ---------------------------------------------------------------------------
// GEMM2 + fused GEMM3 + fused BN-stat/pool (unchanged)
// ---------------------------------------------------------------------------
__global__ __launch_bounds__(256, 1) void mma_gemm2f(
    const __half* __restrict__ C1h, const __half* __restrict__ C1l,
    const __half* __restrict__ H1, long h1_bstr,
    const __half* __restrict__ A1h, const __half* __restrict__ A1l,
    int K,
    const float* __restrict__ bias,
    const float* __restrict__ w1f,
    float* __restrict__ sbc, float* __restrict__ ssbc, float* __restrict__ dotb)
{
    extern __shared__ char dsm[];
    const uint32_t sb = smem_u32(dsm);

    const int tid = threadIdx.x;
    const int wid = tid >> 5, lane = tid & 31;
    const int bz = blockIdx.z;
    const int Aoff = blockIdx.x * 128;

    const __half* p0 = C1h + (size_t)Aoff * K;
    const __half* p1 = C1l + (size_t)Aoff * K;
    const __half* p2 = H1 + (size_t)bz * h1_bstr;
    const __half* a1h_b = A1h + (size_t)bz * NJ * NJ;
    const __half* a1l_b = A1l + (size_t)bz * NJ * NJ;

    const int m_base = (wid >> 2) * 64;
    const int n_base = (wid & 3) * 32;
    const int quad = lane >> 3, id8 = lane & 7;

    uint32_t aoff[4], boff[2];
#pragma unroll
    for (int mt = 0; mt < 4; mt++)
        aoff[mt] = (uint32_t)((m_base + mt * 16 + (quad & 1) * 8 + id8) * RSTR + ((quad >> 1) * 8) * 2);
#pragma unroll
    for (int np = 0; np < 2; np++)
        boff[np] = (uint32_t)((n_base + np * 16 + (quad >> 1) * 8 + id8) * RSTR + ((quad & 1) * 8) * 2);

    float d[4][4][4];
#pragma unroll
    for (int mt = 0; mt < 4; mt++)
#pragma unroll
        for (int nt = 0; nt < 4; nt++)
#pragma unroll
            for (int k = 0; k < 4; k++) d[mt][nt][k] = 0.f;

    const int nk = K / BK;

    load_tile(sb + 0 * TILEB, p0, K, 0);
    load_tile(sb + 1 * TILEB, p1, K, 0);
    load_tile(sb + 2 * TILEB, p2, K, 0);
    CP_COMMIT();
    load_tile(sb + STG3 + 0 * TILEB, p0, K, BK);
    load_tile(sb + STG3 + 1 * TILEB, p1, K, BK);
    load_tile(sb + STG3 + 2 * TILEB, p2, K, BK);
    CP_COMMIT();

    for (int i = 0; i < nk; i++) {
        if (i + 1 < nk) CP_WAIT1(); else CP_WAIT0();
        __syncthreads();
        const uint32_t st = sb + (i & 1) * STG3;

        MMA_STAGE_SA(st);

        __syncthreads();
        if (i + 2 < nk) {
            const uint32_t nstg = sb + (i & 1) * STG3;
            const int k0 = (i + 2) * BK;
            load_tile(nstg + 0 * TILEB, p0, K, k0);
            load_tile(nstg + 1 * TILEB, p1, K, k0);
            load_tile(nstg + 2 * TILEB, p2, K, k0);
            CP_COMMIT();
        }
    }

    // --- fused GEMM3: preload A1 hi/lo into free slots ---
    load_tile(sb + 2 * TILEB, a1h_b, NJ, 0);
    load_tile(sb + 3 * TILEB, a1l_b, NJ, 0);
    load_tile(sb + 4 * TILEB, a1h_b, NJ, 64);
    load_tile(sb + 5 * TILEB, a1l_b, NJ, 64);
    CP_COMMIT();

    // write hs2 tile (+bias, fp16) into A slots, j split across 2 slots
    const int g = lane >> 2, t2 = (lane & 3) * 2;
#pragma unroll
    for (int mt = 0; mt < 4; mt++) {
        const int r0 = m_base + mt * 16 + g;
        const int r1 = r0 + 8;
        const float bv0 = bias[Aoff + r0];
        const float bv1 = bias[Aoff + r1];
#pragma unroll
        for (int nt = 0; nt < 4; nt++) {
            const int col = n_base + nt * 8 + t2;
            const uint32_t cslot = (uint32_t)(col >> 6) * TILEB;
            const uint32_t cl = (uint32_t)(col & 63) * 2;
            __half2 v0 = __floats2half2_rn(d[mt][nt][0] + bv0, d[mt][nt][1] + bv0);
            __half2 v1 = __floats2half2_rn(d[mt][nt][2] + bv1, d[mt][nt][3] + bv1);
            asm volatile("st.shared.b32 [%0], %1;"
                :: "r"(sb + cslot + (uint32_t)r0 * RSTR + cl), "r"(*(uint32_t*)&v0));
            asm volatile("st.shared.b32 [%0], %1;"
                :: "r"(sb + cslot + (uint32_t)r1 * RSTR + cl), "r"(*(uint32_t*)&v1));
        }
    }
    CP_WAIT0();
    __syncthreads();

#pragma unroll
    for (int mt = 0; mt < 4; mt++)
#pragma unroll
        for (int nt = 0; nt < 4; nt++)
#pragma unroll
            for (int k = 0; k < 4; k++) d[mt][nt][k] = 0.f;

    MMA_STAGE_SB3(sb + 0 * TILEB, sb + 2 * TILEB, sb + 3 * TILEB);
    MMA_STAGE_SB3(sb + 1 * TILEB, sb + 4 * TILEB, sb + 5 * TILEB);

    // --- fused BN-stat + pool epilogue ---
    __syncthreads();
    float* red = (float*)dsm;
    const int nw = wid & 3;
#pragma unroll
    for (int mt = 0; mt < 4; mt++) {
        float s0r = 0, ss0 = 0, dt0 = 0, s1r = 0, ss1 = 0, dt1 = 0;
#pragma unroll
        for (int nt = 0; nt < 4; nt++) {
            const int col = n_base + nt * 8 + t2;
            float wa = __ldg(w1f + col), wb = __ldg(w1f + col + 1);
            float v00 = d[mt][nt][0], v01 = d[mt][nt][1];
            float v10 = d[mt][nt][2], v11 = d[mt][nt][3];
            s0r += v00 + v01;  ss0 = fmaf(v00, v00, fmaf(v01, v01, ss0));
            dt0 = fmaf(v00, wa, fmaf(v01, wb, dt0));
            s1r += v10 + v11;  ss1 = fmaf(v10, v10, fmaf(v11, v11, ss1));
            dt1 = fmaf(v10, wa, fmaf(v11, wb, dt1));
        }
#pragma unroll
        for (int o = 2; o > 0; o >>= 1) {
            s0r += __shfl_down_sync(0xffffffffu, s0r, o, 4);
            ss0 += __shfl_down_sync(0xffffffffu, ss0, o, 4);
            dt0 += __shfl_down_sync(0xffffffffu, dt0, o, 4);
            s1r += __shfl_down_sync(0xffffffffu, s1r, o, 4);
            ss1 += __shfl_down_sync(0xffffffffu, ss1, o, 4);
            dt1 += __shfl_down_sync(0xffffffffu, dt1, o, 4);
        }
        if ((lane & 3) == 0) {
            const int r0 = m_base + mt * 16 + g, r1 = r0 + 8;
            red[0 * 512 + nw * 128 + r0] = s0r; red[0 * 512 + nw * 128 + r1] = s1r;
            red[1 * 512 + nw * 128 + r0] = ss0; red[1 * 512 + nw * 128 + r1] = ss1;
            red[2 * 512 + nw * 128 + r0] = dt0; red[2 * 512 + nw * 128 + r1] = dt1;
        }
    }
    __syncthreads();
    if (tid < 128) {
        float s  = red[tid] + red[128 + tid] + red[256 + tid] + red[384 + tid];
        float ss = red[512 + tid] + red[640 + tid] + red[768 + tid] + red[896 + tid];
        float dt = red[1024 + tid] + red[1152 + tid] + red[1280 + tid] + red[1408 + tid];
        const size_t o = (size_t)bz * PS + Aoff + tid;
        sbc[o] = s; ssbc[o] = ss; dotb[o] = dt;
    }
}

// ---------------------------------------------------------------------------
// small kernels
// ---------------------------------------------------------------------------
__global__ void k_wmeans(const float* __restrict__ wq, const float* __restrict__ wk,
                         const float* __restrict__ bq, const float* __restrict__ bk) {
    const int bx = blockIdx.x;
    if (bx < 48) {
        const int tx = threadIdx.x & 31, ty = threadIdx.x >> 5;
        const int c = bx * 32 + tx;
        float sq = 0.f, sk = 0.f;
        for (int o = ty; o < QK; o += 8) {
            sq += wq[(size_t)o * PS + c];
            sk += wk[(size_t)o * PS + c];
        }
        __shared__ float aq[8][32], ak[8][32];
        aq[ty][tx] = sq; ak[ty][tx] = sk;
        __syncthreads();
        if (ty == 0) {
#pragma unroll
            for (int u = 1; u < 8; u++) { sq += aq[u][tx]; sk += ak[u][tx]; }
            g_wqm[c] = sq * (1.0f / QK);
            g_wkm[c] = sk * (1.0f / QK);
        }
    } else if (threadIdx.x < 32) {
        const float* src = (bx == 48) ? bq : bk;
        float s = 0.f;
        for (int o = threadIdx.x; o < QK; o += 32) s += src[o];
#pragma unroll
        for (int o = 16; o > 0; o >>= 1) s += __shfl_down_sync(0xffffffffu, s, o);
        if (threadIdx.x == 0) g_bqkm[bx - 48] = s * (1.0f / QK);
    }
}

// hs4: block (32 b-lanes, 8 c), grid PS/8 = 192
__global__ void k_hs4(const float* __restrict__ gamma, const float* __restrict__ beta,
                      const float* __restrict__ w1, const float* __restrict__ b1) {
    __shared__ float sw红[1];
    __shared__ float sws;
    const int tid = threadIdx.y * 32 + threadIdx.x;
    (void)sw红;
    if (tid < 32) {
        float sw = 0.f;
#pragma unroll
        for (int j = tid; j < NJ; j += 32) sw += w1[j];
#pragma unroll
        for (int o = 16; o > 0; o >>= 1) sw += __shfl_down_sync(0xffffffffu, sw, o);
        if (tid == 0) sws = sw;
    }
    __syncthreads();
    const float sw = sws;
    const int c = blockIdx.x * 8 + threadIdx.y;
    const int b = threadIdx.x;
    const size_t o = (size_t)b * PS + c;
    float s  = g_sbc[o];
    float ss = g_ssbc[o];
    float st = s, sst = ss;
#pragma unroll
    for (int u = 16; u > 0; u >>= 1) {
        st  += __shfl_down_sync(0xffffffffu, st, u);
        sst += __shfl_down_sync(0xffffffffu, sst, u);
    }
    st  = __shfl_sync(0xffffffffu, st, 0);
    sst = __shfl_sync(0xffffffffu, sst, 0);
    const float inv = 1.0f / (BB * NJ);
    float mean = st * inv;
    float var = sst * inv - mean * mean;
    float rstd = rsqrtf(var + 1e-5f);
    float ga = gamma[c] * rstd;
    float be = beta[c] * sw + b1[0];
    float msw = mean * sw;
    g_hs4[b * PS + c] = ga * (g_dotb[o] - msw) + be;
}

__global__ void k_cls(const float* __restrict__ wcls, const float* __restrict__ bcls,
                      float* __restrict__ out) {
    __shared__ __align__(16) float sh[PS];
    const int b = blockIdx.x;
    for (int i = threadIdx.x; i < PS; i += blockDim.x) sh[i] = g_hs4[b * PS + i];
    __syncthreads();
    const int n = threadIdx.x;
    if (n < NC) {
        float acc = bcls[n];
        const float4* w4 = (const float4*)(wcls + (size_t)n * PS);
        const float4* s4 = (const float4*)sh;
        for (int c = 0; c < PS / 4; c++) {
            float4 w = w4[c], s = s4[c];
            acc = fmaf(s.x, w.x, acc);
            acc = fmaf(s.y, w.y, acc);
            acc = fmaf(s.z, w.z, acc);
            acc = fmaf(s.w, w.w, acc);
        }
        out[b * NC + n] = acc;
    }
}

// ---------------------------------------------------------------------------
// launch
// ---------------------------------------------------------------------------
extern "C" void kernel_launch(void* const* d_in, const int* in_sizes, int n_in,
                              void* d_out, int out_size) {
    (void)in_sizes; (void)n_in; (void)out_size;
    const float* x       = (const float*)d_in[0];
    const float* w_pool0 = (const float*)d_in[1];
    const float* b_pool0 = (const float*)d_in[2];
    const float* adj1    = (const float*)d_in[3];
    const float* w_q     = (const float*)d_in[4];
    const float* b_q     = (const float*)d_in[5];
    const float* w_k     = (const float*)d_in[6];
    const float* b_k     = (const float*)d_in[7];
    const float* alpha   = (const float*)d_in[8];
    const float* w_c1    = (const float*)d_in[9];
    const float* b_c1    = (const float*)d_in[10];
    const float* gamma   = (const float*)d_in[11];
    const float* beta    = (const float*)d_in[12];
    const float* w_pool1 = (const float*)d_in[13];
    const float* b_pool1 = (const float*)d_in[14];
    const float* w_cls   = (const float*)d_in[15];
    const float* b_cls   = (const float*)d_in[16];
    float* out = (float*)d_out;

    __half *w0hi, *w0lo, *c1hi, *c1lo, *h1, *a1hi, *a1lo;
    float *sbc, *ssbc, *dotb;
    cudaGetSymbolAddress((void**)&w0hi, g_w0hi);
    cudaGetSymbolAddress((void**)&w0lo, g_w0lo);
    cudaGetSymbolAddress((void**)&c1hi, g_c1hi);
    cudaGetSymbolAddress((void**)&c1lo, g_c1lo);
    cudaGetSymbolAddress((void**)&h1,   g_h1);
    cudaGetSymbolAddress((void**)&a1hi, g_a1hi);
    cudaGetSymbolAddress((void**)&a1lo, g_a1lo);
    cudaGetSymbolAddress((void**)&sbc,  g_sbc);
    cudaGetSymbolAddress((void**)&ssbc, g_ssbc);
    cudaGetSymbolAddress((void**)&dotb, g_dotb);

    const int smem_bytes = 2 * STG3;   // 110592
    cudaFuncSetAttribute(mma_gemm2f, cudaFuncAttributeMaxDynamicSharedMemorySize, smem_bytes);
    cudaFuncSetAttribute(mma_gemm_x, cudaFuncAttributeMaxDynamicSharedMemorySize, smem_bytes);

    // weight hi/lo splits (one launch) + q/k weight means
    k_cvt2<<<(unsigned)((W0_N4 + C1_N4) / 256), 256>>>(w_pool0, w_c1);
    k_wmeans<<<50, 256>>>(w_q, w_k, b_q, b_k);

    // GEMM1 + fused q/k partials
    mma_gemm_x<<<dim3(NCT, 1, BB), 256, smem_bytes>>>(
        w0hi, w0lo,
        x, (long)PS * TNS,
        TNS, b_pool0,
        h1, (long)NJ * PS, PS);

    // q1/k1 reduce + A1^T build (parallel over 8 chunks x 32 batches)
    k_qkA1<<<dim3(8, BB), 256>>>(adj1, alpha);

    // GEMM2 + fused GEMM3 + fused BN-stat/pool
    mma_gemm2f<<<dim3(NCT, 1, BB), 256, smem_bytes>>>(
        c1hi, c1lo,
        h1, (long)NJ * PS,
        a1hi, a1lo,
        PS, b_c1,
        w_pool1, sbc, ssbc, dotb);

    k_hs4<<<PS / 8, dim3(32, 8)>>>(gamma, beta, w_pool1, b_pool1);
    k_cls<<<BB, 256>>>(w_cls, b_cls, out);
}

// round 13
// speedup vs baseline: 1.0739x; 1.0282x over previous
#include <cuda_runtime.h>
#include <cuda_fp16.h>
#include <cstdint>
#include <cstddef>

#define BB   32
#define PS   1536
#define TNS  2048
#define NJ   128
#define QK   384
#define NC   200
#define NCT  12          // c-tiles per batch in GEMM1

// ---------------------------------------------------------------------------
// scratch (static device globals; no allocation)
// ---------------------------------------------------------------------------
__device__ __half g_w0hi[(size_t)NJ * TNS];
__device__ __half g_w0lo[(size_t)NJ * TNS];
__device__ __half g_h1  [(size_t)BB * NJ * PS];   // hs1^T [b][j][c], fp16
__device__ __half g_a1hi[(size_t)BB * NJ * NJ];   // A1^T  [b][k][j]
__device__ __half g_a1lo[(size_t)BB * NJ * NJ];
__device__ float g_qp  [(size_t)BB * NCT * NJ];   // q1 partials per c-tile
__device__ float g_kp  [(size_t)BB * NCT * NJ];
__device__ float g_sbc [(size_t)BB * PS];
__device__ float g_ssbc[(size_t)BB * PS];
__device__ float g_dotb[(size_t)BB * PS];
__device__ float g_wqm[PS];
__device__ float g_wkm[PS];
__device__ float g_bqkm[2];
__device__ float g_hs4[BB * PS];

// ---------------------------------------------------------------------------
// helpers
// ---------------------------------------------------------------------------
__device__ __forceinline__ uint32_t smem_u32(const void* p) {
    uint32_t a;
    asm("{ .reg .u64 t; cvta.to.shared.u64 t, %1; cvt.u32.u64 %0, t; }" : "=r"(a) : "l"(p));
    return a;
}
#define CP_COMMIT() asm volatile("cp.async.commit_group;" ::: "memory")
#define CP_WAIT0()  asm volatile("cp.async.wait_group 0;" ::: "memory")
#define CP_WAIT1()  asm volatile("cp.async.wait_group 1;" ::: "memory")

__device__ __forceinline__ void ld4(uint32_t* r, uint32_t a) {
    asm volatile("ldmatrix.sync.aligned.m8n8.x4.shared.b16 {%0,%1,%2,%3}, [%4];"
        : "=r"(r[0]), "=r"(r[1]), "=r"(r[2]), "=r"(r[3]) : "r"(a));
}
__device__ __forceinline__ void mma16816(float* d, const uint32_t* a, const uint32_t* b) {
    asm volatile(
        "mma.sync.aligned.m16n8k16.row.col.f32.f16.f16.f32 "
        "{%0,%1,%2,%3}, {%4,%5,%6,%7}, {%8,%9}, {%0,%1,%2,%3};"
        : "+f"(d[0]), "+f"(d[1]), "+f"(d[2]), "+f"(d[3])
        : "r"(a[0]), "r"(a[1]), "r"(a[2]), "r"(a[3]), "r"(b[0]), "r"(b[1]));
}

// fp32 -> (hi, lo) fp16 split for w0 only (small)
__global__ void k_cvt_w0(const float* __restrict__ s) {
    long i = (long)blockIdx.x * blockDim.x + threadIdx.x;   // < NJ*TNS/4
    float4 v = ((const float4*)s)[i];
    __half h0 = __float2half_rn(v.x), h1 = __float2half_rn(v.y);
    __half h2 = __float2half_rn(v.z), h3 = __float2half_rn(v.w);
    __half l0 = __float2half_rn(v.x - __half2float(h0));
    __half l1 = __float2half_rn(v.y - __half2float(h1));
    __half l2 = __float2half_rn(v.z - __half2float(h2));
    __half l3 = __float2half_rn(v.w - __half2float(h3));
    __half2 ph0; ph0.x = h0; ph0.y = h1;
    __half2 ph1; ph1.x = h2; ph1.y = h3;
    __half2 pl0; pl0.x = l0; pl0.y = l1;
    __half2 pl1; pl1.x = l2; pl1.y = l3;
    ((__half2*)g_w0hi)[i * 2 + 0] = ph0;
    ((__half2*)g_w0hi)[i * 2 + 1] = ph1;
    ((__half2*)g_w0lo)[i * 2 + 0] = pl0;
    ((__half2*)g_w0lo)[i * 2 + 1] = pl1;
}

// ---------------------------------------------------------------------------
// SMEM tile layout: 2 stages x 3 tiles, 128 rows x 64 k (fp16, 128B/row + 16 pad)
// ---------------------------------------------------------------------------
#define BK    64
#define RSTR  144
#define TILEB (128 * RSTR)     // 18432
#define STG3  (3 * TILEB)      // 55296

__device__ __forceinline__ void load_tile(uint32_t sb, const __half* g, int gstride, int k0) {
    const int t = threadIdx.x;
#pragma unroll
    for (int p = 0; p < 4; p++) {
        int idx = p * 256 + t;
        int row = idx >> 3, ch = idx & 7;
        uint32_t dst = sb + row * RSTR + ch * 16;
        const void* src = g + (size_t)row * gstride + k0 + ch * 8;
        asm volatile("cp.async.cg.shared.global [%0], [%1], 16;" :: "r"(dst), "l"(src));
    }
}

// 2-term MMA over one stage (4 k16 steps), split-A: tile0=Ah, tile1=Al, tile2=B
#define MMA_STAGE_SA(st)                                                         \
    do {                                                                         \
        _Pragma("unroll")                                                        \
        for (int ks = 0; ks < 4; ks++) {                                         \
            const uint32_t klo = ks * 32;                                        \
            uint32_t ah[4][4], bf[2][4];                                         \
            _Pragma("unroll")                                                    \
            for (int mt = 0; mt < 4; mt++) ld4(ah[mt], (st) + 0 * TILEB + aoff[mt] + klo); \
            _Pragma("unroll")                                                    \
            for (int np = 0; np < 2; np++) ld4(bf[np], (st) + 2 * TILEB + boff[np] + klo); \
            _Pragma("unroll")                                                    \
            for (int mt = 0; mt < 4; mt++)                                       \
                _Pragma("unroll")                                                \
                for (int nt = 0; nt < 4; nt++)                                   \
                    mma16816(d[mt][nt], ah[mt], &bf[nt >> 1][(nt & 1) * 2]);     \
            {                                                                    \
                uint32_t al[4][4];                                               \
                _Pragma("unroll")                                                \
                for (int mt = 0; mt < 4; mt++) ld4(al[mt], (st) + 1 * TILEB + aoff[mt] + klo); \
                _Pragma("unroll")                                                \
                for (int mt = 0; mt < 4; mt++)                                   \
                    _Pragma("unroll")                                            \
                    for (int nt = 0; nt < 4; nt++)                               \
                        mma16816(d[mt][nt], al[mt], &bf[nt >> 1][(nt & 1) * 2]); \
            }                                                                    \
        }                                                                        \
    } while (0)

// 2-term MMA over one 64-k chunk, explicit slots: A single, B hi/lo
#define MMA_STAGE_SB3(sA, sBh, sBl)                                              \
    do {                                                                         \
        _Pragma("unroll")                                                        \
        for (int ks = 0; ks < 4; ks++) {                                         \
            const uint32_t klo = ks * 32;                                        \
            uint32_t af[4][4], bh[2][4];                                         \
            _Pragma("unroll")                                                    \
            for (int mt = 0; mt < 4; mt++) ld4(af[mt], (sA) + aoff[mt] + klo);   \
            _Pragma("unroll")                                                    \
            for (int np = 0; np < 2; np++) ld4(bh[np], (sBh) + boff[np] + klo);  \
            _Pragma("unroll")                                                    \
            for (int mt = 0; mt < 4; mt++)                                       \
                _Pragma("unroll")                                                \
                for (int nt = 0; nt < 4; nt++)                                   \
                    mma16816(d[mt][nt], af[mt], &bh[nt >> 1][(nt & 1) * 2]);     \
            {                                                                    \
                uint32_t bl[2][4];                                               \
                _Pragma("unroll")                                                \
                for (int np = 0; np < 2; np++) ld4(bl[np], (sBl) + boff[np] + klo); \
                _Pragma("unroll")                                                \
                for (int mt = 0; mt < 4; mt++)                                   \
                    _Pragma("unroll")                                            \
                    for (int nt = 0; nt < 4; nt++)                               \
                        mma16816(d[mt][nt], af[mt], &bl[nt >> 1][(nt & 1) * 2]); \
            }                                                                    \
        }                                                                        \
    } while (0)

// fp32 LDG of a 128x64 chunk into registers (8 x float4 per thread)
__device__ __forceinline__ void ldgF(float4* br, const float* pB, int K, int k0) {
    const int t = threadIdx.x;
#pragma unroll
    for (int p = 0; p < 8; p++) {
        int idx = p * 256 + t;
        int row = idx >> 4, f4 = idx & 15;
        br[p] = *(const float4*)(pB + (size_t)row * K + k0 + f4 * 4);
    }
}
// fp16-round STS into ONE tile slot (used by gemm_x for B = x)
__device__ __forceinline__ void cvt_sts1(const float4* br, uint32_t slot) {
    const int t = threadIdx.x;
#pragma unroll
    for (int p = 0; p < 8; p++) {
        int idx = p * 256 + t;
        int row = idx >> 4, f4 = idx & 15;
        float4 v = br[p];
        __half2 h01 = __floats2half2_rn(v.x, v.y);
        __half2 h23 = __floats2half2_rn(v.z, v.w);
        uint32_t off = (uint32_t)(row * RSTR + f4 * 8);
        asm volatile("st.shared.v2.b32 [%0], {%1,%2};"
            :: "r"(slot + off), "r"(*(uint32_t*)&h01), "r"(*(uint32_t*)&h23));
    }
}
// hi/lo split STS into TWO tile slots (used by gemm2f for A = w_c1)
__device__ __forceinline__ void cvt_sts2(const float4* br, uint32_t st) {
    const int t = threadIdx.x;
#pragma unroll
    for (int p = 0; p < 8; p++) {
        int idx = p * 256 + t;
        int row = idx >> 4, f4 = idx & 15;
        float4 v = br[p];
        __half2 h01 = __floats2half2_rn(v.x, v.y);
        __half2 h23 = __floats2half2_rn(v.z, v.w);
        float2 hf01 = __half22float2(h01);
        float2 hf23 = __half22float2(h23);
        __half2 l01 = __floats2half2_rn(v.x - hf01.x, v.y - hf01.y);
        __half2 l23 = __floats2half2_rn(v.z - hf23.x, v.w - hf23.y);
        uint32_t off = (uint32_t)(row * RSTR + f4 * 8);
        asm volatile("st.shared.v2.b32 [%0], {%1,%2};"
            :: "r"(st + off), "r"(*(uint32_t*)&h01), "r"(*(uint32_t*)&h23));
        asm volatile("st.shared.v2.b32 [%0], {%1,%2};"
            :: "r"(st + TILEB + off), "r"(*(uint32_t*)&l01), "r"(*(uint32_t*)&l23));
    }
}

// ---------------------------------------------------------------------------
// GEMM1: hs1^T[j, c-tile] = (w0h + w0l)[j,:] . x_fp16[b, c,:]  + fused q/k partials
// ---------------------------------------------------------------------------
__global__ __launch_bounds__(256, 1) void mma_gemm_x(
    const __half* __restrict__ Ah, const __half* __restrict__ Al,
    const float* __restrict__ Bf, long b_bstr,
    int K,
    const float* __restrict__ bias,
    __half* __restrict__ oh,
    long o_bstr, int o_rstr)
{
    extern __shared__ char dsm[];
    const uint32_t sb = smem_u32(dsm);

    const int tid = threadIdx.x;
    const int wid = tid >> 5, lane = tid & 31;
    const int bz = blockIdx.z;
    const int Boff = blockIdx.x * 128;
    const float* pBf = Bf + (size_t)bz * b_bstr + (size_t)Boff * K;

    const int m_base = (wid >> 2) * 64;
    const int n_base = (wid & 3) * 32;
    const int quad = lane >> 3, id8 = lane & 7;

    uint32_t aoff[4], boff[2];
#pragma unroll
    for (int mt = 0; mt < 4; mt++)
        aoff[mt] = (uint32_t)((m_base + mt * 16 + (quad & 1) * 8 + id8) * RSTR + ((quad >> 1) * 8) * 2);
#pragma unroll
    for (int np = 0; np < 2; np++)
        boff[np] = (uint32_t)((n_base + np * 16 + (quad >> 1) * 8 + id8) * RSTR + ((quad & 1) * 8) * 2);

    float d[4][4][4];
#pragma unroll
    for (int mt = 0; mt < 4; mt++)
#pragma unroll
        for (int nt = 0; nt < 4; nt++)
#pragma unroll
            for (int k = 0; k < 4; k++) d[mt][nt][k] = 0.f;

    const int nk = K / BK;
    float4 breg[8];

    // prologue: chunk0 + chunk1 staged
    ldgF(breg, pBf, K, 0);
    cvt_sts1(breg, sb + 2 * TILEB);
    load_tile(sb + 0 * TILEB, Ah, K, 0);
    load_tile(sb + 1 * TILEB, Al, K, 0);
    CP_COMMIT();
    ldgF(breg, pBf, K, BK);
    cvt_sts1(breg, sb + STG3 + 2 * TILEB);
    load_tile(sb + STG3 + 0 * TILEB, Ah, K, BK);
    load_tile(sb + STG3 + 1 * TILEB, Al, K, BK);
    CP_COMMIT();
    CP_WAIT1();
    __syncthreads();

    for (int i = 0; i < nk; i++) {
        const uint32_t st = sb + (i & 1) * STG3;
        if (i + 2 < nk) ldgF(breg, pBf, K, (i + 2) * BK);

        MMA_STAGE_SA(st);

        __syncthreads();                      // stage (i&1) free
        if (i + 2 < nk) {
            cvt_sts1(breg, st + 2 * TILEB);
            load_tile(st + 0 * TILEB, Ah, K, (i + 2) * BK);
            load_tile(st + 1 * TILEB, Al, K, (i + 2) * BK);
            CP_COMMIT();
        }
        if (i + 1 < nk) {
            if (i + 2 < nk) CP_WAIT1(); else CP_WAIT0();
            __syncthreads();                  // stage (i+1) ready
        }
    }

    // epilogue: write fp16 hs1^T AND fused q/k partial sums over this c-tile
    __syncthreads();                          // smem free for reduction reuse
    float* red = (float*)dsm;                 // [2][4][128]
    const int g = lane >> 2, t2 = (lane & 3) * 2;
    const int nw = wid & 3;
#pragma unroll
    for (int mt = 0; mt < 4; mt++) {
        const int r0 = m_base + mt * 16 + g;
        const int r1 = r0 + 8;
        const float bv0 = bias[r0];
        const float bv1 = bias[r1];
        const size_t base0 = (size_t)bz * o_bstr + (size_t)r0 * o_rstr + Boff;
        const size_t base1 = (size_t)bz * o_bstr + (size_t)r1 * o_rstr + Boff;
        float pq0 = 0.f, pk0 = 0.f, pq1 = 0.f, pk1 = 0.f;
#pragma unroll
        for (int nt = 0; nt < 4; nt++) {
            const int col = n_base + nt * 8 + t2;
            float v00 = d[mt][nt][0] + bv0, v01 = d[mt][nt][1] + bv0;
            float v10 = d[mt][nt][2] + bv1, v11 = d[mt][nt][3] + bv1;
            *(__half2*)(oh + base0 + col) = __floats2half2_rn(v00, v01);
            *(__half2*)(oh + base1 + col) = __floats2half2_rn(v10, v11);
            float wqa = g_wqm[Boff + col], wqb = g_wqm[Boff + col + 1];
            float wka = g_wkm[Boff + col], wkb = g_wkm[Boff + col + 1];
            pq0 = fmaf(v00, wqa, fmaf(v01, wqb, pq0));
            pk0 = fmaf(v00, wka, fmaf(v01, wkb, pk0));
            pq1 = fmaf(v10, wqa, fmaf(v11, wqb, pq1));
            pk1 = fmaf(v10, wka, fmaf(v11, wkb, pk1));
        }
#pragma unroll
        for (int o = 2; o > 0; o >>= 1) {
            pq0 += __shfl_down_sync(0xffffffffu, pq0, o, 4);
            pk0 += __shfl_down_sync(0xffffffffu, pk0, o, 4);
            pq1 += __shfl_down_sync(0xffffffffu, pq1, o, 4);
            pk1 += __shfl_down_sync(0xffffffffu, pk1, o, 4);
        }
        if ((lane & 3) == 0) {
            red[0 * 512 + nw * 128 + r0] = pq0; red[0 * 512 + nw * 128 + r1] = pq1;
            red[1 * 512 + nw * 128 + r0] = pk0; red[1 * 512 + nw * 128 + r1] = pk1;
        }
    }
    __syncthreads();
    if (tid < 128) {
        float q = red[tid] + red[128 + tid] + red[256 + tid] + red[384 + tid];
        float k = red[512 + tid] + red[640 + tid] + red[768 + tid] + red[896 + tid];
        const size_t o = ((size_t)bz * NCT + blockIdx.x) * NJ + tid;
        g_qp[o] = q;
        g_kp[o] = k;
    }
}

// ---------------------------------------------------------------------------
// q1/k1 from partials + A1^T hi/lo; grid (8, BB)
// ---------------------------------------------------------------------------
__global__ void k_qkA1(const float* __restrict__ adj, const float* __restrict__ alpha) {
    __shared__ float q1s[NJ], k1s[NJ];
    const int b = blockIdx.y, tid = threadIdx.x;
    if (tid < 128) {
        float q = g_bqkm[0], k = g_bqkm[1];
#pragma unroll
        for (int t = 0; t < NCT; t++) {
            q += g_qp[((size_t)b * NCT + t) * NJ + tid];
            k += g_kp[((size_t)b * NCT + t) * NJ + tid];
        }
        q1s[tid] = q; k1s[tid] = k;
    }
    __syncthreads();
    const float a = alpha[0];
    const int base = blockIdx.x * 2048;
#pragma unroll
    for (int u = 0; u < 8; u++) {
        const int idx = base + u * 256 + tid;
        const int k = idx >> 7, j = idx & 127;
        float v = adj[j * NJ + k] + tanhf(q1s[j] - k1s[k]) * a;
        __half h = __float2half_rn(v);
        __half l = __float2half_rn(v - __half2float(h));
        g_a1hi[(size_t)b * NJ * NJ + idx] = h;
        g_a1lo[(size_t)b * NJ * NJ + idx] = l;
    }
}

// ---------------------------------------------------------------------------
// GEMM2 (A = w_c1 fp32, converted in-kernel) + fused GEMM3 + fused BN-stat/pool
// ---------------------------------------------------------------------------
__global__ __launch_bounds__(256, 1) void mma_gemm2f(
    const float* __restrict__ C1f,
    const __half* __restrict__ H1, long h1_bstr,
    const __half* __restrict__ A1h, const __half* __restrict__ A1l,
    int K,
    const float* __restrict__ bias,
    const float* __restrict__ w1f,
    float* __restrict__ sbc, float* __restrict__ ssbc, float* __restrict__ dotb)
{
    extern __shared__ char dsm[];
    const uint32_t sb = smem_u32(dsm);

    const int tid = threadIdx.x;
    const int wid = tid >> 5, lane = tid & 31;
    const int bz = blockIdx.z;
    const int Aoff = blockIdx.x * 128;

    const float* pAf = C1f + (size_t)Aoff * K;
    const __half* p2 = H1 + (size_t)bz * h1_bstr;
    const __half* a1h_b = A1h + (size_t)bz * NJ * NJ;
    const __half* a1l_b = A1l + (size_t)bz * NJ * NJ;

    const int m_base = (wid >> 2) * 64;
    const int n_base = (wid & 3) * 32;
    const int quad = lane >> 3, id8 = lane & 7;

    uint32_t aoff[4], boff[2];
#pragma unroll
    for (int mt = 0; mt < 4; mt++)
        aoff[mt] = (uint32_t)((m_base + mt * 16 + (quad & 1) * 8 + id8) * RSTR + ((quad >> 1) * 8) * 2);
#pragma unroll
    for (int np = 0; np < 2; np++)
        boff[np] = (uint32_t)((n_base + np * 16 + (quad >> 1) * 8 + id8) * RSTR + ((quad & 1) * 8) * 2);

    float d[4][4][4];
#pragma unroll
    for (int mt = 0; mt < 4; mt++)
#pragma unroll
        for (int nt = 0; nt < 4; nt++)
#pragma unroll
            for (int k = 0; k < 4; k++) d[mt][nt][k] = 0.f;

    const int nk = K / BK;
    float4 breg[8];

    // prologue: chunk0 + chunk1 staged (gemm_x-style; A via ldg+split, B via cp.async)
    ldgF(breg, pAf, K, 0);
    cvt_sts2(breg, sb);
    load_tile(sb + 2 * TILEB, p2, K, 0);
    CP_COMMIT();
    ldgF(breg, pAf, K, BK);
    cvt_sts2(breg, sb + STG3);
    load_tile(sb + STG3 + 2 * TILEB, p2, K, BK);
    CP_COMMIT();
    CP_WAIT1();
    __syncthreads();

    for (int i = 0; i < nk; i++) {
        const uint32_t st = sb + (i & 1) * STG3;
        if (i + 2 < nk) ldgF(breg, pAf, K, (i + 2) * BK);

        MMA_STAGE_SA(st);

        __syncthreads();                      // stage (i&1) free
        if (i + 2 < nk) {
            cvt_sts2(breg, st);
            load_tile(st + 2 * TILEB, p2, K, (i + 2) * BK);
            CP_COMMIT();
        }
        if (i + 1 < nk) {
            if (i + 2 < nk) CP_WAIT1(); else CP_WAIT0();
            __syncthreads();                  // stage (i+1) ready
        }
    }

    // --- fused GEMM3: preload A1 hi/lo into free slots ---
    load_tile(sb + 2 * TILEB, a1h_b, NJ, 0);
    load_tile(sb + 3 * TILEB, a1l_b, NJ, 0);
    load_tile(sb + 4 * TILEB, a1h_b, NJ, 64);
    load_tile(sb + 5 * TILEB, a1l_b, NJ, 64);
    CP_COMMIT();

    // write hs2 tile (+bias, fp16) into A slots, j split across 2 slots
    const int g = lane >> 2, t2 = (lane & 3) * 2;
#pragma unroll
    for (int mt = 0; mt < 4; mt++) {
        const int r0 = m_base + mt * 16 + g;
        const int r1 = r0 + 8;
        const float bv0 = bias[Aoff + r0];
        const float bv1 = bias[Aoff + r1];
#pragma unroll
        for (int nt = 0; nt < 4; nt++) {
            const int col = n_base + nt * 8 + t2;
            const uint32_t cslot = (uint32_t)(col >> 6) * TILEB;
            const uint32_t cl = (uint32_t)(col & 63) * 2;
            __half2 v0 = __floats2half2_rn(d[mt][nt][0] + bv0, d[mt][nt][1] + bv0);
            __half2 v1 = __floats2half2_rn(d[mt][nt][2] + bv1, d[mt][nt][3] + bv1);
            asm volatile("st.shared.b32 [%0], %1;"
                :: "r"(sb + cslot + (uint32_t)r0 * RSTR + cl), "r"(*(uint32_t*)&v0));
            asm volatile("st.shared.b32 [%0], %1;"
                :: "r"(sb + cslot + (uint32_t)r1 * RSTR + cl), "r"(*(uint32_t*)&v1));
        }
    }
    CP_WAIT0();
    __syncthreads();

#pragma unroll
    for (int mt = 0; mt < 4; mt++)
#pragma unroll
        for (int nt = 0; nt < 4; nt++)
#pragma unroll
            for (int k = 0; k < 4; k++) d[mt][nt][k] = 0.f;

    MMA_STAGE_SB3(sb + 0 * TILEB, sb + 2 * TILEB, sb + 3 * TILEB);
    MMA_STAGE_SB3(sb + 1 * TILEB, sb + 4 * TILEB, sb + 5 * TILEB);

    // --- fused BN-stat + pool epilogue ---
    __syncthreads();
    float* red = (float*)dsm;
    const int nw = wid & 3;
#pragma unroll
    for (int mt = 0; mt < 4; mt++) {
        float s0r = 0, ss0 = 0, dt0 = 0, s1r = 0, ss1 = 0, dt1 = 0;
#pragma unroll
        for (int nt = 0; nt < 4; nt++) {
            const int col = n_base + nt * 8 + t2;
            float wa = __ldg(w1f + col), wb = __ldg(w1f + col + 1);
            float v00 = d[mt][nt][0], v01 = d[mt][nt][1];
            float v10 = d[mt][nt][2], v11 = d[mt][nt][3];
            s0r += v00 + v01;  ss0 = fmaf(v00, v00, fmaf(v01, v01, ss0));
            dt0 = fmaf(v00, wa, fmaf(v01, wb, dt0));
            s1r += v10 + v11;  ss1 = fmaf(v10, v10, fmaf(v11, v11, ss1));
            dt1 = fmaf(v10, wa, fmaf(v11, wb, dt1));
        }
#pragma unroll
        for (int o = 2; o > 0; o >>= 1) {
            s0r += __shfl_down_sync(0xffffffffu, s0r, o, 4);
            ss0 += __shfl_down_sync(0xffffffffu, ss0, o, 4);
            dt0 += __shfl_down_sync(0xffffffffu, dt0, o, 4);
            s1r += __shfl_down_sync(0xffffffffu, s1r, o, 4);
            ss1 += __shfl_down_sync(0xffffffffu, ss1, o, 4);
            dt1 += __shfl_down_sync(0xffffffffu, dt1, o, 4);
        }
        if ((lane & 3) == 0) {
            const int r0 = m_base + mt * 16 + g, r1 = r0 + 8;
            red[0 * 512 + nw * 128 + r0] = s0r; red[0 * 512 + nw * 128 + r1] = s1r;
            red[1 * 512 + nw * 128 + r0] = ss0; red[1 * 512 + nw * 128 + r1] = ss1;
            red[2 * 512 + nw * 128 + r0] = dt0; red[2 * 512 + nw * 128 + r1] = dt1;
        }
    }
    __syncthreads();
    if (tid < 128) {
        float s  = red[tid] + red[128 + tid] + red[256 + tid] + red[384 + tid];
        float ss = red[512 + tid] + red[640 + tid] + red[768 + tid] + red[896 + tid];
        float dt = red[1024 + tid] + red[1152 + tid] + red[1280 + tid] + red[1408 + tid];
        const size_t o = (size_t)bz * PS + Aoff + tid;
        sbc[o] = s; ssbc[o] = ss; dotb[o] = dt;
    }
}

// ---------------------------------------------------------------------------
// small kernels
// ---------------------------------------------------------------------------
__global__ void k_wmeans(const float* __restrict__ wq, const float* __restrict__ wk,
                         const float* __restrict__ bq, const float* __restrict__ bk) {
    const int bx = blockIdx.x;
    if (bx < 48) {
        const int tx = threadIdx.x & 31, ty = threadIdx.x >> 5;
        const int c = bx * 32 + tx;
        float sq = 0.f, sk = 0.f;
        for (int o = ty; o < QK; o += 8) {
            sq += wq[(size_t)o * PS + c];
            sk += wk[(size_t)o * PS + c];
        }
        __shared__ float aq[8][32], ak[8][32];
        aq[ty][tx] = sq; ak[ty][tx] = sk;
        __syncthreads();
        if (ty == 0) {
#pragma unroll
            for (int u = 1; u < 8; u++) { sq += aq[u][tx]; sk += ak[u][tx]; }
            g_wqm[c] = sq * (1.0f / QK);
            g_wkm[c] = sk * (1.0f / QK);
        }
    } else if (threadIdx.x < 32) {
        const float* src = (bx == 48) ? bq : bk;
        float s = 0.f;
        for (int o = threadIdx.x; o < QK; o += 32) s += src[o];
#pragma unroll
        for (int o = 16; o > 0; o >>= 1) s += __shfl_down_sync(0xffffffffu, s, o);
        if (threadIdx.x == 0) g_bqkm[bx - 48] = s * (1.0f / QK);
    }
}

// hs4: block (32 b-lanes, 8 c), grid PS/8 = 192
__global__ void k_hs4(const float* __restrict__ gamma, const float* __restrict__ beta,
                      const float* __restrict__ w1, const float* __restrict__ b1) {
    __shared__ float sws;
    const int tid = threadIdx.y * 32 + threadIdx.x;
    if (tid < 32) {
        float sw = 0.f;
#pragma unroll
        for (int j = tid; j < NJ; j += 32) sw += w1[j];
#pragma unroll
        for (int o = 16; o > 0; o >>= 1) sw += __shfl_down_sync(0xffffffffu, sw, o);
        if (tid == 0) sws = sw;
    }
    __syncthreads();
    const float sw = sws;
    const int c = blockIdx.x * 8 + threadIdx.y;
    const int b = threadIdx.x;
    const size_t o = (size_t)b * PS + c;
    float st  = g_sbc[o];
    float sst = g_ssbc[o];
#pragma unroll
    for (int u = 16; u > 0; u >>= 1) {
        st  += __shfl_down_sync(0xffffffffu, st, u);
        sst += __shfl_down_sync(0xffffffffu, sst, u);
    }
    st  = __shfl_sync(0xffffffffu, st, 0);
    sst = __shfl_sync(0xffffffffu, sst, 0);
    const float inv = 1.0f / (BB * NJ);
    float mean = st * inv;
    float var = sst * inv - mean * mean;
    float rstd = rsqrtf(var + 1e-5f);
    float ga = gamma[c] * rstd;
    float be = beta[c] * sw + b1[0];
    float msw = mean * sw;
    g_hs4[b * PS + c] = ga * (g_dotb[o] - msw) + be;
}

__global__ void k_cls(const float* __restrict__ wcls, const float* __restrict__ bcls,
                      float* __restrict__ out) {
    __shared__ __align__(16) float sh[PS];
    const int b = blockIdx.x;
    for (int i = threadIdx.x; i < PS; i += blockDim.x) sh[i] = g_hs4[b * PS + i];
    __syncthreads();
    const int n = threadIdx.x;
    if (n < NC) {
        float acc = bcls[n];
        const float4* w4 = (const float4*)(wcls + (size_t)n * PS);
        const float4* s4 = (const float4*)sh;
        for (int c = 0; c < PS / 4; c++) {
            float4 w = w4[c], s = s4[c];
            acc = fmaf(s.x, w.x, acc);
            acc = fmaf(s.y, w.y, acc);
            acc = fmaf(s.z, w.z, acc);
            acc = fmaf(s.w, w.w, acc);
        }
        out[b * NC + n] = acc;
    }
}

// ---------------------------------------------------------------------------
// launch
// ---------------------------------------------------------------------------
extern "C" void kernel_launch(void* const* d_in, const int* in_sizes, int n_in,
                              void* d_out, int out_size) {
    (void)in_sizes; (void)n_in; (void)out_size;
    const float* x       = (const float*)d_in[0];
    const float* w_pool0 = (const float*)d_in[1];
    const float* b_pool0 = (const float*)d_in[2];
    const float* adj1    = (const float*)d_in[3];
    const float* w_q     = (const float*)d_in[4];
    const float* b_q     = (const float*)d_in[5];
    const float* w_k     = (const float*)d_in[6];
    const float* b_k     = (const float*)d_in[7];
    const float* alpha   = (const float*)d_in[8];
    const float* w_c1    = (const float*)d_in[9];
    const float* b_c1    = (const float*)d_in[10];
    const float* gamma   = (const float*)d_in[11];
    const float* beta    = (const float*)d_in[12];
    const float* w_pool1 = (const float*)d_in[13];
    const float* b_pool1 = (const float*)d_in[14];
    const float* w_cls   = (const float*)d_in[15];
    const float* b_cls   = (const float*)d_in[16];
    float* out = (float*)d_out;

    __half *w0hi, *w0lo, *h1, *a1hi, *a1lo;
    float *sbc, *ssbc, *dotb;
    cudaGetSymbolAddress((void**)&w0hi, g_w0hi);
    cudaGetSymbolAddress((void**)&w0lo, g_w0lo);
    cudaGetSymbolAddress((void**)&h1,   g_h1);
    cudaGetSymbolAddress((void**)&a1hi, g_a1hi);
    cudaGetSymbolAddress((void**)&a1lo, g_a1lo);
    cudaGetSymbolAddress((void**)&sbc,  g_sbc);
    cudaGetSymbolAddress((void**)&ssbc, g_ssbc);
    cudaGetSymbolAddress((void**)&dotb, g_dotb);

    const int smem_bytes = 2 * STG3;   // 110592
    cudaFuncSetAttribute(mma_gemm2f, cudaFuncAttributeMaxDynamicSharedMemorySize, smem_bytes);
    cudaFuncSetAttribute(mma_gemm_x, cudaFuncAttributeMaxDynamicSharedMemorySize, smem_bytes);

    // w0 hi/lo split + q/k weight means (both tiny, both before gemm_x)
    k_cvt_w0<<<(unsigned)((long)NJ * TNS / 4 / 256), 256>>>(w_pool0);
    k_wmeans<<<50, 256>>>(w_q, w_k, b_q, b_k);

    // GEMM1 + fused q/k partials
    mma_gemm_x<<<dim3(NCT, 1, BB), 256, smem_bytes>>>(
        w0hi, w0lo,
        x, (long)PS * TNS,
        TNS, b_pool0,
        h1, (long)NJ * PS, PS);

    // q1/k1 reduce + A1^T build
    k_qkA1<<<dim3(8, BB), 256>>>(adj1, alpha);

    // GEMM2 (inline c1 conversion) + fused GEMM3 + fused BN-stat/pool
    mma_gemm2f<<<dim3(NCT, 1, BB), 256, smem_bytes>>>(
        w_c1,
        h1, (long)NJ * PS,
        a1hi, a1lo,
        PS, b_c1,
        w_pool1, sbc, ssbc, dotb);

    k_hs4<<<PS / 8, dim3(32, 8)>>>(gamma, beta, w_pool1, b_pool1);
    k_cls<<<BB, 256>>>(w_cls, b_cls, out);
}

// round 14
// speedup vs baseline: 1.2550x; 1.1686x over previous
#include <cuda_runtime.h>
#include <cuda_fp16.h>
#include <cstdint>
#include <cstddef>

#define BB   32
#define PS   1536
#define TNS  2048
#define NJ   128
#define QK   384
#define NC   200
#define NCT  12          // c-tiles per batch in GEMM1

// ---------------------------------------------------------------------------
// scratch (static device globals; no allocation)
// ---------------------------------------------------------------------------
__device__ __half g_w0h [(size_t)NJ * TNS];       // w0 rounded fp16 (1-term)
__device__ __half g_h1  [(size_t)BB * NJ * PS];   // hs1^T [b][j][c], fp16
__device__ __half g_a1hi[(size_t)BB * NJ * NJ];   // A1^T  [b][k][j]
__device__ __half g_a1lo[(size_t)BB * NJ * NJ];
__device__ float g_qp  [(size_t)BB * NCT * NJ];   // q1 partials per c-tile
__device__ float g_kp  [(size_t)BB * NCT * NJ];
__device__ float g_sbc [(size_t)BB * PS];
__device__ float g_ssbc[(size_t)BB * PS];
__device__ float g_dotb[(size_t)BB * PS];
__device__ float g_wqm[PS];
__device__ float g_wkm[PS];
__device__ float g_bqkm[2];
__device__ float g_hs4[BB * PS];

// ---------------------------------------------------------------------------
// helpers
// ---------------------------------------------------------------------------
__device__ __forceinline__ uint32_t smem_u32(const void* p) {
    uint32_t a;
    asm("{ .reg .u64 t; cvta.to.shared.u64 t, %1; cvt.u32.u64 %0, t; }" : "=r"(a) : "l"(p));
    return a;
}
#define CP_COMMIT() asm volatile("cp.async.commit_group;" ::: "memory")
#define CP_WAIT0()  asm volatile("cp.async.wait_group 0;" ::: "memory")
#define CP_WAIT1()  asm volatile("cp.async.wait_group 1;" ::: "memory")

__device__ __forceinline__ void ld4(uint32_t* r, uint32_t a) {
    asm volatile("ldmatrix.sync.aligned.m8n8.x4.shared.b16 {%0,%1,%2,%3}, [%4];"
        : "=r"(r[0]), "=r"(r[1]), "=r"(r[2]), "=r"(r[3]) : "r"(a));
}
__device__ __forceinline__ void mma16816(float* d, const uint32_t* a, const uint32_t* b) {
    asm volatile(
        "mma.sync.aligned.m16n8k16.row.col.f32.f16.f16.f32 "
        "{%0,%1,%2,%3}, {%4,%5,%6,%7}, {%8,%9}, {%0,%1,%2,%3};"
        : "+f"(d[0]), "+f"(d[1]), "+f"(d[2]), "+f"(d[3])
        : "r"(a[0]), "r"(a[1]), "r"(a[2]), "r"(a[3]), "r"(b[0]), "r"(b[1]));
}

// fp32 -> fp16 round for w0 (1-term path)
__global__ void k_cvt_w0(const float* __restrict__ s) {
    long i = (long)blockIdx.x * blockDim.x + threadIdx.x;   // < NJ*TNS/4
    float4 v = ((const float4*)s)[i];
    __half2 h01 = __floats2half2_rn(v.x, v.y);
    __half2 h23 = __floats2half2_rn(v.z, v.w);
    ((__half2*)g_w0h)[i * 2 + 0] = h01;
    ((__half2*)g_w0h)[i * 2 + 1] = h23;
}

// ---------------------------------------------------------------------------
// SMEM tile: 128 rows x 64 k fp16, 128B/row + 16 pad
// ---------------------------------------------------------------------------
#define BK    64
#define RSTR  144
#define TILEB (128 * RSTR)     // 18432
#define STG2  (2 * TILEB)      // gemm_x stage (A, B)
#define STG3  (3 * TILEB)      // gemm2f stage (Ah, Al, B)

__device__ __forceinline__ void load_tile(uint32_t sb, const __half* g, int gstride, int k0) {
    const int t = threadIdx.x;
#pragma unroll
    for (int p = 0; p < 4; p++) {
        int idx = p * 256 + t;
        int row = idx >> 3, ch = idx & 7;
        uint32_t dst = sb + row * RSTR + ch * 16;
        const void* src = g + (size_t)row * gstride + k0 + ch * 8;
        asm volatile("cp.async.cg.shared.global [%0], [%1], 16;" :: "r"(dst), "l"(src));
    }
}

// 1-term MMA over one stage: tile0 = A, tile1 = B
#define MMA_STAGE_1T(st)                                                         \
    do {                                                                         \
        _Pragma("unroll")                                                        \
        for (int ks = 0; ks < 4; ks++) {                                         \
            const uint32_t klo = ks * 32;                                        \
            uint32_t ah[4][4], bf[2][4];                                         \
            _Pragma("unroll")                                                    \
            for (int mt = 0; mt < 4; mt++) ld4(ah[mt], (st) + 0 * TILEB + aoff[mt] + klo); \
            _Pragma("unroll")                                                    \
            for (int np = 0; np < 2; np++) ld4(bf[np], (st) + 1 * TILEB + boff[np] + klo); \
            _Pragma("unroll")                                                    \
            for (int mt = 0; mt < 4; mt++)                                       \
                _Pragma("unroll")                                                \
                for (int nt = 0; nt < 4; nt++)                                   \
                    mma16816(d[mt][nt], ah[mt], &bf[nt >> 1][(nt & 1) * 2]);     \
        }                                                                        \
    } while (0)

// 2-term MMA over one stage, split-A: tile0=Ah, tile1=Al, tile2=B
#define MMA_STAGE_SA(st)                                                         \
    do {                                                                         \
        _Pragma("unroll")                                                        \
        for (int ks = 0; ks < 4; ks++) {                                         \
            const uint32_t klo = ks * 32;                                        \
            uint32_t ah[4][4], bf[2][4];                                         \
            _Pragma("unroll")                                                    \
            for (int mt = 0; mt < 4; mt++) ld4(ah[mt], (st) + 0 * TILEB + aoff[mt] + klo); \
            _Pragma("unroll")                                                    \
            for (int np = 0; np < 2; np++) ld4(bf[np], (st) + 2 * TILEB + boff[np] + klo); \
            _Pragma("unroll")                                                    \
            for (int mt = 0; mt < 4; mt++)                                       \
                _Pragma("unroll")                                                \
                for (int nt = 0; nt < 4; nt++)                                   \
                    mma16816(d[mt][nt], ah[mt], &bf[nt >> 1][(nt & 1) * 2]);     \
            {                                                                    \
                uint32_t al[4][4];                                               \
                _Pragma("unroll")                                                \
                for (int mt = 0; mt < 4; mt++) ld4(al[mt], (st) + 1 * TILEB + aoff[mt] + klo); \
                _Pragma("unroll")                                                \
                for (int mt = 0; mt < 4; mt++)                                   \
                    _Pragma("unroll")                                            \
                    for (int nt = 0; nt < 4; nt++)                               \
                        mma16816(d[mt][nt], al[mt], &bf[nt >> 1][(nt & 1) * 2]); \
            }                                                                    \
        }                                                                        \
    } while (0)

// 2-term MMA over one 64-k chunk, explicit slots: A single, B hi/lo
#define MMA_STAGE_SB3(sA, sBh, sBl)                                              \
    do {                                                                         \
        _Pragma("unroll")                                                        \
        for (int ks = 0; ks < 4; ks++) {                                         \
            const uint32_t klo = ks * 32;                                        \
            uint32_t af[4][4], bh[2][4];                                         \
            _Pragma("unroll")                                                    \
            for (int mt = 0; mt < 4; mt++) ld4(af[mt], (sA) + aoff[mt] + klo);   \
            _Pragma("unroll")                                                    \
            for (int np = 0; np < 2; np++) ld4(bh[np], (sBh) + boff[np] + klo);  \
            _Pragma("unroll")                                                    \
            for (int mt = 0; mt < 4; mt++)                                       \
                _Pragma("unroll")                                                \
                for (int nt = 0; nt < 4; nt++)                                   \
                    mma16816(d[mt][nt], af[mt], &bh[nt >> 1][(nt & 1) * 2]);     \
            {                                                                    \
                uint32_t bl[2][4];                                               \
                _Pragma("unroll")                                                \
                for (int np = 0; np < 2; np++) ld4(bl[np], (sBl) + boff[np] + klo); \
                _Pragma("unroll")                                                \
                for (int mt = 0; mt < 4; mt++)                                   \
                    _Pragma("unroll")                                            \
                    for (int nt = 0; nt < 4; nt++)                               \
                        mma16816(d[mt][nt], af[mt], &bl[nt >> 1][(nt & 1) * 2]); \
            }                                                                    \
        }                                                                        \
    } while (0)

// fp32 LDG of a 128x64 chunk into registers (8 x float4 per thread)
__device__ __forceinline__ void ldgF(float4* br, const float* pB, int K, int k0) {
    const int t = threadIdx.x;
#pragma unroll
    for (int p = 0; p < 8; p++) {
        int idx = p * 256 + t;
        int row = idx >> 4, f4 = idx & 15;
        br[p] = *(const float4*)(pB + (size_t)row * K + k0 + f4 * 4);
    }
}
// fp16-round STS into ONE tile slot
__device__ __forceinline__ void cvt_sts1(const float4* br, uint32_t slot) {
    const int t = threadIdx.x;
#pragma unroll
    for (int p = 0; p < 8; p++) {
        int idx = p * 256 + t;
        int row = idx >> 4, f4 = idx & 15;
        float4 v = br[p];
        __half2 h01 = __floats2half2_rn(v.x, v.y);
        __half2 h23 = __floats2half2_rn(v.z, v.w);
        uint32_t off = (uint32_t)(row * RSTR + f4 * 8);
        asm volatile("st.shared.v2.b32 [%0], {%1,%2};"
            :: "r"(slot + off), "r"(*(uint32_t*)&h01), "r"(*(uint32_t*)&h23));
    }
}
// hi/lo split STS into TWO tile slots (gemm2f A = w_c1)
__device__ __forceinline__ void cvt_sts2(const float4* br, uint32_t st) {
    const int t = threadIdx.x;
#pragma unroll
    for (int p = 0; p < 8; p++) {
        int idx = p * 256 + t;
        int row = idx >> 4, f4 = idx & 15;
        float4 v = br[p];
        __half2 h01 = __floats2half2_rn(v.x, v.y);
        __half2 h23 = __floats2half2_rn(v.z, v.w);
        float2 hf01 = __half22float2(h01);
        float2 hf23 = __half22float2(h23);
        __half2 l01 = __floats2half2_rn(v.x - hf01.x, v.y - hf01.y);
        __half2 l23 = __floats2half2_rn(v.z - hf23.x, v.w - hf23.y);
        uint32_t off = (uint32_t)(row * RSTR + f4 * 8);
        asm volatile("st.shared.v2.b32 [%0], {%1,%2};"
            :: "r"(st + off), "r"(*(uint32_t*)&h01), "r"(*(uint32_t*)&h23));
        asm volatile("st.shared.v2.b32 [%0], {%1,%2};"
            :: "r"(st + TILEB + off), "r"(*(uint32_t*)&l01), "r"(*(uint32_t*)&l23));
    }
}

// ---------------------------------------------------------------------------
// GEMM1 (1-term): hs1^T[j, c-tile] = w0_fp16[j,:] . x_fp16[b, c,:] + fused q/k partials
// ---------------------------------------------------------------------------
__global__ __launch_bounds__(256, 1) void mma_gemm_x(
    const __half* __restrict__ Ah,
    const float* __restrict__ Bf, long b_bstr,
    int K,
    const float* __restrict__ bias,
    __half* __restrict__ oh,
    long o_bstr, int o_rstr)
{
    extern __shared__ char dsm[];
    const uint32_t sb = smem_u32(dsm);

    const int tid = threadIdx.x;
    const int wid = tid >> 5, lane = tid & 31;
    const int bz = blockIdx.z;
    const int Boff = blockIdx.x * 128;
    const float* pBf = Bf + (size_t)bz * b_bstr + (size_t)Boff * K;

    const int m_base = (wid >> 2) * 64;
    const int n_base = (wid & 3) * 32;
    const int quad = lane >> 3, id8 = lane & 7;

    uint32_t aoff[4], boff[2];
#pragma unroll
    for (int mt = 0; mt < 4; mt++)
        aoff[mt] = (uint32_t)((m_base + mt * 16 + (quad & 1) * 8 + id8) * RSTR + ((quad >> 1) * 8) * 2);
#pragma unroll
    for (int np = 0; np < 2; np++)
        boff[np] = (uint32_t)((n_base + np * 16 + (quad >> 1) * 8 + id8) * RSTR + ((quad & 1) * 8) * 2);

    float d[4][4][4];
#pragma unroll
    for (int mt = 0; mt < 4; mt++)
#pragma unroll
        for (int nt = 0; nt < 4; nt++)
#pragma unroll
            for (int k = 0; k < 4; k++) d[mt][nt][k] = 0.f;

    const int nk = K / BK;
    float4 breg[8];

    // prologue: chunk0 + chunk1 staged
    ldgF(breg, pBf, K, 0);
    cvt_sts1(breg, sb + 1 * TILEB);
    load_tile(sb + 0 * TILEB, Ah, K, 0);
    CP_COMMIT();
    ldgF(breg, pBf, K, BK);
    cvt_sts1(breg, sb + STG2 + 1 * TILEB);
    load_tile(sb + STG2 + 0 * TILEB, Ah, K, BK);
    CP_COMMIT();
    CP_WAIT1();
    __syncthreads();

    for (int i = 0; i < nk; i++) {
        const uint32_t st = sb + (i & 1) * STG2;
        if (i + 2 < nk) ldgF(breg, pBf, K, (i + 2) * BK);

        MMA_STAGE_1T(st);

        __syncthreads();                      // stage (i&1) free
        if (i + 2 < nk) {
            cvt_sts1(breg, st + 1 * TILEB);
            load_tile(st + 0 * TILEB, Ah, K, (i + 2) * BK);
            CP_COMMIT();
        }
        if (i + 1 < nk) {
            if (i + 2 < nk) CP_WAIT1(); else CP_WAIT0();
            __syncthreads();                  // stage (i+1) ready
        }
    }

    // epilogue: write fp16 hs1^T AND fused q/k partial sums over this c-tile
    __syncthreads();
    float* red = (float*)dsm;                 // [2][4][128]
    const int g = lane >> 2, t2 = (lane & 3) * 2;
    const int nw = wid & 3;
#pragma unroll
    for (int mt = 0; mt < 4; mt++) {
        const int r0 = m_base + mt * 16 + g;
        const int r1 = r0 + 8;
        const float bv0 = bias[r0];
        const float bv1 = bias[r1];
        const size_t base0 = (size_t)bz * o_bstr + (size_t)r0 * o_rstr + Boff;
        const size_t base1 = (size_t)bz * o_bstr + (size_t)r1 * o_rstr + Boff;
        float pq0 = 0.f, pk0 = 0.f, pq1 = 0.f, pk1 = 0.f;
#pragma unroll
        for (int nt = 0; nt < 4; nt++) {
            const int col = n_base + nt * 8 + t2;
            float v00 = d[mt][nt][0] + bv0, v01 = d[mt][nt][1] + bv0;
            float v10 = d[mt][nt][2] + bv1, v11 = d[mt][nt][3] + bv1;
            *(__half2*)(oh + base0 + col) = __floats2half2_rn(v00, v01);
            *(__half2*)(oh + base1 + col) = __floats2half2_rn(v10, v11);
            float wqa = g_wqm[Boff + col], wqb = g_wqm[Boff + col + 1];
            float wka = g_wkm[Boff + col], wkb = g_wkm[Boff + col + 1];
            pq0 = fmaf(v00, wqa, fmaf(v01, wqb, pq0));
            pk0 = fmaf(v00, wka, fmaf(v01, wkb, pk0));
            pq1 = fmaf(v10, wqa, fmaf(v11, wqb, pq1));
            pk1 = fmaf(v10, wka, fmaf(v11, wkb, pk1));
        }
#pragma unroll
        for (int o = 2; o > 0; o >>= 1) {
            pq0 += __shfl_down_sync(0xffffffffu, pq0, o, 4);
            pk0 += __shfl_down_sync(0xffffffffu, pk0, o, 4);
            pq1 += __shfl_down_sync(0xffffffffu, pq1, o, 4);
            pk1 += __shfl_down_sync(0xffffffffu, pk1, o, 4);
        }
        if ((lane & 3) == 0) {
            red[0 * 512 + nw * 128 + r0] = pq0; red[0 * 512 + nw * 128 + r1] = pq1;
            red[1 * 512 + nw * 128 + r0] = pk0; red[1 * 512 + nw * 128 + r1] = pk1;
        }
    }
    __syncthreads();
    if (tid < 128) {
        float q = red[tid] + red[128 + tid] + red[256 + tid] + red[384 + tid];
        float k = red[512 + tid] + red[640 + tid] + red[768 + tid] + red[896 + tid];
        const size_t o = ((size_t)bz * NCT + blockIdx.x) * NJ + tid;
        g_qp[o] = q;
        g_kp[o] = k;
    }
}

// ---------------------------------------------------------------------------
// q1/k1 from partials + A1^T hi/lo; grid (8, BB)
// ---------------------------------------------------------------------------
__global__ void k_qkA1(const float* __restrict__ adj, const float* __restrict__ alpha) {
    __shared__ float q1s[NJ], k1s[NJ];
    const int b = blockIdx.y, tid = threadIdx.x;
    if (tid < 128) {
        float q = g_bqkm[0], k = g_bqkm[1];
#pragma unroll
        for (int t = 0; t < NCT; t++) {
            q += g_qp[((size_t)b * NCT + t) * NJ + tid];
            k += g_kp[((size_t)b * NCT + t) * NJ + tid];
        }
        q1s[tid] = q; k1s[tid] = k;
    }
    __syncthreads();
    const float a = alpha[0];
    const int base = blockIdx.x * 2048;
#pragma unroll
    for (int u = 0; u < 8; u++) {
        const int idx = base + u * 256 + tid;
        const int k = idx >> 7, j = idx & 127;
        float v = adj[j * NJ + k] + tanhf(q1s[j] - k1s[k]) * a;
        __half h = __float2half_rn(v);
        __half l = __float2half_rn(v - __half2float(h));
        g_a1hi[(size_t)b * NJ * NJ + idx] = h;
        g_a1lo[(size_t)b * NJ * NJ + idx] = l;
    }
}

// ---------------------------------------------------------------------------
// GEMM2 (A = w_c1 fp32, converted in-kernel) + fused GEMM3 + fused BN-stat/pool
// ---------------------------------------------------------------------------
__global__ __launch_bounds__(256, 1) void mma_gemm2f(
    const float* __restrict__ C1f,
    const __half* __restrict__ H1, long h1_bstr,
    const __half* __restrict__ A1h, const __half* __restrict__ A1l,
    int K,
    const float* __restrict__ bias,
    const float* __restrict__ w1f,
    float* __restrict__ sbc, float* __restrict__ ssbc, float* __restrict__ dotb)
{
    extern __shared__ char dsm[];
    const uint32_t sb = smem_u32(dsm);

    const int tid = threadIdx.x;
    const int wid = tid >> 5, lane = tid & 31;
    const int bz = blockIdx.z;
    const int Aoff = blockIdx.x * 128;

    const float* pAf = C1f + (size_t)Aoff * K;
    const __half* p2 = H1 + (size_t)bz * h1_bstr;
    const __half* a1h_b = A1h + (size_t)bz * NJ * NJ;
    const __half* a1l_b = A1l + (size_t)bz * NJ * NJ;

    const int m_base = (wid >> 2) * 64;
    const int n_base = (wid & 3) * 32;
    const int quad = lane >> 3, id8 = lane & 7;

    uint32_t aoff[4], boff[2];
#pragma unroll
    for (int mt = 0; mt < 4; mt++)
        aoff[mt] = (uint32_t)((m_base + mt * 16 + (quad & 1) * 8 + id8) * RSTR + ((quad >> 1) * 8) * 2);
#pragma unroll
    for (int np = 0; np < 2; np++)
        boff[np] = (uint32_t)((n_base + np * 16 + (quad >> 1) * 8 + id8) * RSTR + ((quad & 1) * 8) * 2);

    float d[4][4][4];
#pragma unroll
    for (int mt = 0; mt < 4; mt++)
#pragma unroll
        for (int nt = 0; nt < 4; nt++)
#pragma unroll
            for (int k = 0; k < 4; k++) d[mt][nt][k] = 0.f;

    const int nk = K / BK;
    float4 breg[8];

    // prologue
    ldgF(breg, pAf, K, 0);
    cvt_sts2(breg, sb);
    load_tile(sb + 2 * TILEB, p2, K, 0);
    CP_COMMIT();
    ldgF(breg, pAf, K, BK);
    cvt_sts2(breg, sb + STG3);
    load_tile(sb + STG3 + 2 * TILEB, p2, K, BK);
    CP_COMMIT();
    CP_WAIT1();
    __syncthreads();

    for (int i = 0; i < nk; i++) {
        const uint32_t st = sb + (i & 1) * STG3;
        if (i + 2 < nk) ldgF(breg, pAf, K, (i + 2) * BK);

        MMA_STAGE_SA(st);

        __syncthreads();
        if (i + 2 < nk) {
            cvt_sts2(breg, st);
            load_tile(st + 2 * TILEB, p2, K, (i + 2) * BK);
            CP_COMMIT();
        }
        if (i + 1 < nk) {
            if (i + 2 < nk) CP_WAIT1(); else CP_WAIT0();
            __syncthreads();
        }
    }

    // --- fused GEMM3: preload A1 hi/lo into free slots ---
    load_tile(sb + 2 * TILEB, a1h_b, NJ, 0);
    load_tile(sb + 3 * TILEB, a1l_b, NJ, 0);
    load_tile(sb + 4 * TILEB, a1h_b, NJ, 64);
    load_tile(sb + 5 * TILEB, a1l_b, NJ, 64);
    CP_COMMIT();

    // write hs2 tile (+bias, fp16) into A slots, j split across 2 slots
    const int g = lane >> 2, t2 = (lane & 3) * 2;
#pragma unroll
    for (int mt = 0; mt < 4; mt++) {
        const int r0 = m_base + mt * 16 + g;
        const int r1 = r0 + 8;
        const float bv0 = bias[Aoff + r0];
        const float bv1 = bias[Aoff + r1];
#pragma unroll
        for (int nt = 0; nt < 4; nt++) {
            const int col = n_base + nt * 8 + t2;
            const uint32_t cslot = (uint32_t)(col >> 6) * TILEB;
            const uint32_t cl = (uint32_t)(col & 63) * 2;
            __half2 v0 = __floats2half2_rn(d[mt][nt][0] + bv0, d[mt][nt][1] + bv0);
            __half2 v1 = __floats2half2_rn(d[mt][nt][2] + bv1, d[mt][nt][3] + bv1);
            asm volatile("st.shared.b32 [%0], %1;"
                :: "r"(sb + cslot + (uint32_t)r0 * RSTR + cl), "r"(*(uint32_t*)&v0));
            asm volatile("st.shared.b32 [%0], %1;"
                :: "r"(sb + cslot + (uint32_t)r1 * RSTR + cl), "r"(*(uint32_t*)&v1));
        }
    }
    CP_WAIT0();
    __syncthreads();

#pragma unroll
    for (int mt = 0; mt < 4; mt++)
#pragma unroll
        for (int nt = 0; nt < 4; nt++)
#pragma unroll
            for (int k = 0; k < 4; k++) d[mt][nt][k] = 0.f;

    MMA_STAGE_SB3(sb + 0 * TILEB, sb + 2 * TILEB, sb + 3 * TILEB);
    MMA_STAGE_SB3(sb + 1 * TILEB, sb + 4 * TILEB, sb + 5 * TILEB);

    // --- fused BN-stat + pool epilogue ---
    __syncthreads();
    float* red = (float*)dsm;
    const int nw = wid & 3;
#pragma unroll
    for (int mt = 0; mt < 4; mt++) {
        float s0r = 0, ss0 = 0, dt0 = 0, s1r = 0, ss1 = 0, dt1 = 0;
#pragma unroll
        for (int nt = 0; nt < 4; nt++) {
            const int col = n_base + nt * 8 + t2;
            float wa = __ldg(w1f + col), wb = __ldg(w1f + col + 1);
            float v00 = d[mt][nt][0], v01 = d[mt][nt][1];
            float v10 = d[mt][nt][2], v11 = d[mt][nt][3];
            s0r += v00 + v01;  ss0 = fmaf(v00, v00, fmaf(v01, v01, ss0));
            dt0 = fmaf(v00, wa, fmaf(v01, wb, dt0));
            s1r += v10 + v11;  ss1 = fmaf(v10, v10, fmaf(v11, v11, ss1));
            dt1 = fmaf(v10, wa, fmaf(v11, wb, dt1));
        }
#pragma unroll
        for (int o = 2; o > 0; o >>= 1) {
            s0r += __shfl_down_sync(0xffffffffu, s0r, o, 4);
            ss0 += __shfl_down_sync(0xffffffffu, ss0, o, 4);
            dt0 += __shfl_down_sync(0xffffffffu, dt0, o, 4);
            s1r += __shfl_down_sync(0xffffffffu, s1r, o, 4);
            ss1 += __shfl_down_sync(0xffffffffu, ss1, o, 4);
            dt1 += __shfl_down_sync(0xffffffffu, dt1, o, 4);
        }
        if ((lane & 3) == 0) {
            const int r0 = m_base + mt * 16 + g, r1 = r0 + 8;
            red[0 * 512 + nw * 128 + r0] = s0r; red[0 * 512 + nw * 128 + r1] = s1r;
            red[1 * 512 + nw * 128 + r0] = ss0; red[1 * 512 + nw * 128 + r1] = ss1;
            red[2 * 512 + nw * 128 + r0] = dt0; red[2 * 512 + nw * 128 + r1] = dt1;
        }
    }
    __syncthreads();
    if (tid < 128) {
        float s  = red[tid] + red[128 + tid] + red[256 + tid] + red[384 + tid];
        float ss = red[512 + tid] + red[640 + tid] + red[768 + tid] + red[896 + tid];
        float dt = red[1024 + tid] + red[1152 + tid] + red[1280 + tid] + red[1408 + tid];
        const size_t o = (size_t)bz * PS + Aoff + tid;
        sbc[o] = s; ssbc[o] = ss; dotb[o] = dt;
    }
}

// ---------------------------------------------------------------------------
// small kernels
// ---------------------------------------------------------------------------
__global__ void k_wmeans(const float* __restrict__ wq, const float* __restrict__ wk,
                         const float* __restrict__ bq, const float* __restrict__ bk) {
    const int bx = blockIdx.x;
    if (bx < 48) {
        const int tx = threadIdx.x & 31, ty = threadIdx.x >> 5;
        const int c = bx * 32 + tx;
        float sq = 0.f, sk = 0.f;
        for (int o = ty; o < QK; o += 8) {
            sq += wq[(size_t)o * PS + c];
            sk += wk[(size_t)o * PS + c];
        }
        __shared__ float aq[8][32], ak[8][32];
        aq[ty][tx] = sq; ak[ty][tx] = sk;
        __syncthreads();
        if (ty == 0) {
#pragma unroll
            for (int u = 1; u < 8; u++) { sq += aq[u][tx]; sk += ak[u][tx]; }
            g_wqm[c] = sq * (1.0f / QK);
            g_wkm[c] = sk * (1.0f / QK);
        }
    } else if (threadIdx.x < 32) {
        const float* src = (bx == 48) ? bq : bk;
        float s = 0.f;
        for (int o = threadIdx.x; o < QK; o += 32) s += src[o];
#pragma unroll
        for (int o = 16; o > 0; o >>= 1) s += __shfl_down_sync(0xffffffffu, s, o);
        if (threadIdx.x == 0) g_bqkm[bx - 48] = s * (1.0f / QK);
    }
}

// hs4: block (32 b-lanes, 8 c), grid PS/8 = 192
__global__ void k_hs4(const float* __restrict__ gamma, const float* __restrict__ beta,
                      const float* __restrict__ w1, const float* __restrict__ b1) {
    __shared__ float sws;
    const int tid = threadIdx.y * 32 + threadIdx.x;
    if (tid < 32) {
        float sw = 0.f;
#pragma unroll
        for (int j = tid; j < NJ; j += 32) sw += w1[j];
#pragma unroll
        for (int o = 16; o > 0; o >>= 1) sw += __shfl_down_sync(0xffffffffu, sw, o);
        if (tid == 0) sws = sw;
    }
    __syncthreads();
    const float sw = sws;
    const int c = blockIdx.x * 8 + threadIdx.y;
    const int b = threadIdx.x;
    const size_t o = (size_t)b * PS + c;
    float st  = g_sbc[o];
    float sst = g_ssbc[o];
#pragma unroll
    for (int u = 16; u > 0; u >>= 1) {
        st  += __shfl_down_sync(0xffffffffu, st, u);
        sst += __shfl_down_sync(0xffffffffu, sst, u);
    }
    st  = __shfl_sync(0xffffffffu, st, 0);
    sst = __shfl_sync(0xffffffffu, sst, 0);
    const float inv = 1.0f / (BB * NJ);
    float mean = st * inv;
    float var = sst * inv - mean * mean;
    float rstd = rsqrtf(var + 1e-5f);
    float ga = gamma[c] * rstd;
    float be = beta[c] * sw + b1[0];
    float msw = mean * sw;
    g_hs4[b * PS + c] = ga * (g_dotb[o] - msw) + be;
}

__global__ void k_cls(const float* __restrict__ wcls, const float* __restrict__ bcls,
                      float* __restrict__ out) {
    __shared__ __align__(16) float sh[PS];
    const int b = blockIdx.x;
    for (int i = threadIdx.x; i < PS; i += blockDim.x) sh[i] = g_hs4[b * PS + i];
    __syncthreads();
    const int n = threadIdx.x;
    if (n < NC) {
        float acc = bcls[n];
        const float4* w4 = (const float4*)(wcls + (size_t)n * PS);
        const float4* s4 = (const float4*)sh;
        for (int c = 0; c < PS / 4; c++) {
            float4 w = w4[c], s = s4[c];
            acc = fmaf(s.x, w.x, acc);
            acc = fmaf(s.y, w.y, acc);
            acc = fmaf(s.z, w.z, acc);
            acc = fmaf(s.w, w.w, acc);
        }
        out[b * NC + n] = acc;
    }
}

// ---------------------------------------------------------------------------
// launch
// ---------------------------------------------------------------------------
extern "C" void kernel_launch(void* const* d_in, const int* in_sizes, int n_in,
                              void* d_out, int out_size) {
    (void)in_sizes; (void)n_in; (void)out_size;
    const float* x       = (const float*)d_in[0];
    const float* w_pool0 = (const float*)d_in[1];
    const float* b_pool0 = (const float*)d_in[2];
    const float* adj1    = (const float*)d_in[3];
    const float* w_q     = (const float*)d_in[4];
    const float* b_q     = (const float*)d_in[5];
    const float* w_k     = (const float*)d_in[6];
    const float* b_k     = (const float*)d_in[7];
    const float* alpha   = (const float*)d_in[8];
    const float* w_c1    = (const float*)d_in[9];
    const float* b_c1    = (const float*)d_in[10];
    const float* gamma   = (const float*)d_in[11];
    const float* beta    = (const float*)d_in[12];
    const float* w_pool1 = (const float*)d_in[13];
    const float* b_pool1 = (const float*)d_in[14];
    const float* w_cls   = (const float*)d_in[15];
    const float* b_cls   = (const float*)d_in[16];
    float* out = (float*)d_out;

    __half *w0h, *h1, *a1hi, *a1lo;
    float *sbc, *ssbc, *dotb;
    cudaGetSymbolAddress((void**)&w0h,  g_w0h);
    cudaGetSymbolAddress((void**)&h1,   g_h1);
    cudaGetSymbolAddress((void**)&a1hi, g_a1hi);
    cudaGetSymbolAddress((void**)&a1lo, g_a1lo);
    cudaGetSymbolAddress((void**)&sbc,  g_sbc);
    cudaGetSymbolAddress((void**)&ssbc, g_ssbc);
    cudaGetSymbolAddress((void**)&dotb, g_dotb);

    const int smem_x  = 2 * STG2;   // 73728
    const int smem_2f = 2 * STG3;   // 110592
    cudaFuncSetAttribute(mma_gemm2f, cudaFuncAttributeMaxDynamicSharedMemorySize, smem_2f);
    cudaFuncSetAttribute(mma_gemm_x, cudaFuncAttributeMaxDynamicSharedMemorySize, smem_x);

    // w0 fp16 round + q/k weight means
    k_cvt_w0<<<(unsigned)((long)NJ * TNS / 4 / 256), 256>>>(w_pool0);
    k_wmeans<<<50, 256>>>(w_q, w_k, b_q, b_k);

    // GEMM1 (1-term) + fused q/k partials
    mma_gemm_x<<<dim3(NCT, 1, BB), 256, smem_x>>>(
        w0h,
        x, (long)PS * TNS,
        TNS, b_pool0,
        h1, (long)NJ * PS, PS);

    // q1/k1 reduce + A1^T build
    k_qkA1<<<dim3(8, BB), 256>>>(adj1, alpha);

    // GEMM2 (inline c1 conversion, 2-term) + fused GEMM3 + fused BN-stat/pool
    mma_gemm2f<<<dim3(NCT, 1, BB), 256, smem_2f>>>(
        w_c1,
        h1, (long)NJ * PS,
        a1hi, a1lo,
        PS, b_c1,
        w_pool1, sbc, ssbc, dotb);

    k_hs4<<<PS / 8, dim3(32, 8)>>>(gamma, beta, w_pool1, b_pool1);
    k_cls<<<BB, 256>>>(w_cls, b_cls, out);
}

// round 15
// speedup vs baseline: 1.4294x; 1.1389x over previous
#include <cuda_runtime.h>
#include <cuda_fp16.h>
#include <cstdint>
#include <cstddef>

#define BB   32
#define PS   1536
#define TNS  2048
#define NJ   128
#define QK   384
#define NC   200
#define NCT  12          // c-tiles per batch in GEMM1

// ---------------------------------------------------------------------------
// scratch (static device globals; no allocation)
// ---------------------------------------------------------------------------
__device__ __half g_w0h [(size_t)NJ * TNS];       // w0 rounded fp16
__device__ __half g_h1  [(size_t)BB * NJ * PS];   // hs1^T [b][j][c], fp16
__device__ __half g_a1hi[(size_t)BB * NJ * NJ];   // A1^T  [b][k][j]
__device__ __half g_a1lo[(size_t)BB * NJ * NJ];
__device__ float g_qp  [(size_t)BB * NCT * NJ];
__device__ float g_kp  [(size_t)BB * NCT * NJ];
__device__ float g_sbc [(size_t)BB * PS];
__device__ float g_ssbc[(size_t)BB * PS];
__device__ float g_dotb[(size_t)BB * PS];
__device__ float g_wqm[PS];
__device__ float g_wkm[PS];
__device__ float g_bqkm[2];
__device__ float g_hs4[BB * PS];

// ---------------------------------------------------------------------------
// helpers
// ---------------------------------------------------------------------------
__device__ __forceinline__ uint32_t smem_u32(const void* p) {
    uint32_t a;
    asm("{ .reg .u64 t; cvta.to.shared.u64 t, %1; cvt.u32.u64 %0, t; }" : "=r"(a) : "l"(p));
    return a;
}
#define CP_COMMIT() asm volatile("cp.async.commit_group;" ::: "memory")
#define CP_WAIT0()  asm volatile("cp.async.wait_group 0;" ::: "memory")
#define CP_WAIT1()  asm volatile("cp.async.wait_group 1;" ::: "memory")

__device__ __forceinline__ void ld4(uint32_t* r, uint32_t a) {
    asm volatile("ldmatrix.sync.aligned.m8n8.x4.shared.b16 {%0,%1,%2,%3}, [%4];"
        : "=r"(r[0]), "=r"(r[1]), "=r"(r[2]), "=r"(r[3]) : "r"(a));
}
__device__ __forceinline__ void mma16816(float* d, const uint32_t* a, const uint32_t* b) {
    asm volatile(
        "mma.sync.aligned.m16n8k16.row.col.f32.f16.f16.f32 "
        "{%0,%1,%2,%3}, {%4,%5,%6,%7}, {%8,%9}, {%0,%1,%2,%3};"
        : "+f"(d[0]), "+f"(d[1]), "+f"(d[2]), "+f"(d[3])
        : "r"(a[0]), "r"(a[1]), "r"(a[2]), "r"(a[3]), "r"(b[0]), "r"(b[1]));
}

// fp32 -> fp16 round for w0
__global__ void k_cvt_w0(const float* __restrict__ s) {
    long i = (long)blockIdx.x * blockDim.x + threadIdx.x;
    float4 v = ((const float4*)s)[i];
    __half2 h01 = __floats2half2_rn(v.x, v.y);
    __half2 h23 = __floats2half2_rn(v.z, v.w);
    ((__half2*)g_w0h)[i * 2 + 0] = h01;
    ((__half2*)g_w0h)[i * 2 + 1] = h23;
}

// ---------------------------------------------------------------------------
// SMEM tile: 128 rows x 64 k fp16, 128B/row + 16 pad
// ---------------------------------------------------------------------------
#define BK    64
#define RSTR  144
#define TILEB (128 * RSTR)     // 18432
#define STG2  (2 * TILEB)      // mainloop stage (A, B) for both GEMMs

__device__ __forceinline__ void load_tile(uint32_t sb, const __half* g, int gstride, int k0) {
    const int t = threadIdx.x;
#pragma unroll
    for (int p = 0; p < 4; p++) {
        int idx = p * 256 + t;
        int row = idx >> 3, ch = idx & 7;
        uint32_t dst = sb + row * RSTR + ch * 16;
        const void* src = g + (size_t)row * gstride + k0 + ch * 8;
        asm volatile("cp.async.cg.shared.global [%0], [%1], 16;" :: "r"(dst), "l"(src));
    }
}

// 1-term MMA over one stage: tile0 = A, tile1 = B
#define MMA_STAGE_1T(st)                                                         \
    do {                                                                         \
        _Pragma("unroll")                                                        \
        for (int ks = 0; ks < 4; ks++) {                                         \
            const uint32_t klo = ks * 32;                                        \
            uint32_t ah[4][4], bf[2][4];                                         \
            _Pragma("unroll")                                                    \
            for (int mt = 0; mt < 4; mt++) ld4(ah[mt], (st) + 0 * TILEB + aoff[mt] + klo); \
            _Pragma("unroll")                                                    \
            for (int np = 0; np < 2; np++) ld4(bf[np], (st) + 1 * TILEB + boff[np] + klo); \
            _Pragma("unroll")                                                    \
            for (int mt = 0; mt < 4; mt++)                                       \
                _Pragma("unroll")                                                \
                for (int nt = 0; nt < 4; nt++)                                   \
                    mma16816(d[mt][nt], ah[mt], &bf[nt >> 1][(nt & 1) * 2]);     \
        }                                                                        \
    } while (0)

// 2-term MMA over one 64-k chunk, explicit slots: A single, B hi/lo (fused GEMM3)
#define MMA_STAGE_SB3(sA, sBh, sBl)                                              \
    do {                                                                         \
        _Pragma("unroll")                                                        \
        for (int ks = 0; ks < 4; ks++) {                                         \
            const uint32_t klo = ks * 32;                                        \
            uint32_t af[4][4], bh[2][4];                                         \
            _Pragma("unroll")                                                    \
            for (int mt = 0; mt < 4; mt++) ld4(af[mt], (sA) + aoff[mt] + klo);   \
            _Pragma("unroll")                                                    \
            for (int np = 0; np < 2; np++) ld4(bh[np], (sBh) + boff[np] + klo);  \
            _Pragma("unroll")                                                    \
            for (int mt = 0; mt < 4; mt++)                                       \
                _Pragma("unroll")                                                \
                for (int nt = 0; nt < 4; nt++)                                   \
                    mma16816(d[mt][nt], af[mt], &bh[nt >> 1][(nt & 1) * 2]);     \
            {                                                                    \
                uint32_t bl[2][4];                                               \
                _Pragma("unroll")                                                \
                for (int np = 0; np < 2; np++) ld4(bl[np], (sBl) + boff[np] + klo); \
                _Pragma("unroll")                                                \
                for (int mt = 0; mt < 4; mt++)                                   \
                    _Pragma("unroll")                                            \
                    for (int nt = 0; nt < 4; nt++)                               \
                        mma16816(d[mt][nt], af[mt], &bl[nt >> 1][(nt & 1) * 2]); \
            }                                                                    \
        }                                                                        \
    } while (0)

// fp32 LDG of a 128x64 chunk into registers (8 x float4 per thread)
__device__ __forceinline__ void ldgF(float4* br, const float* pB, int K, int k0) {
    const int t = threadIdx.x;
#pragma unroll
    for (int p = 0; p < 8; p++) {
        int idx = p * 256 + t;
        int row = idx >> 4, f4 = idx & 15;
        br[p] = *(const float4*)(pB + (size_t)row * K + k0 + f4 * 4);
    }
}
// fp16-round STS into ONE tile slot
__device__ __forceinline__ void cvt_sts1(const float4* br, uint32_t slot) {
    const int t = threadIdx.x;
#pragma unroll
    for (int p = 0; p < 8; p++) {
        int idx = p * 256 + t;
        int row = idx >> 4, f4 = idx & 15;
        float4 v = br[p];
        __half2 h01 = __floats2half2_rn(v.x, v.y);
        __half2 h23 = __floats2half2_rn(v.z, v.w);
        uint32_t off = (uint32_t)(row * RSTR + f4 * 8);
        asm volatile("st.shared.v2.b32 [%0], {%1,%2};"
            :: "r"(slot + off), "r"(*(uint32_t*)&h01), "r"(*(uint32_t*)&h23));
    }
}

// ---------------------------------------------------------------------------
// GEMM1 (1-term): hs1^T[j, c-tile] = w0_fp16[j,:] . x_fp16[b, c,:] + fused q/k partials
// ---------------------------------------------------------------------------
__global__ __launch_bounds__(256, 1) void mma_gemm_x(
    const __half* __restrict__ Ah,
    const float* __restrict__ Bf, long b_bstr,
    int K,
    const float* __restrict__ bias,
    __half* __restrict__ oh,
    long o_bstr, int o_rstr)
{
    extern __shared__ char dsm[];
    const uint32_t sb = smem_u32(dsm);

    const int tid = threadIdx.x;
    const int wid = tid >> 5, lane = tid & 31;
    const int bz = blockIdx.z;
    const int Boff = blockIdx.x * 128;
    const float* pBf = Bf + (size_t)bz * b_bstr + (size_t)Boff * K;

    const int m_base = (wid >> 2) * 64;
    const int n_base = (wid & 3) * 32;
    const int quad = lane >> 3, id8 = lane & 7;

    uint32_t aoff[4], boff[2];
#pragma unroll
    for (int mt = 0; mt < 4; mt++)
        aoff[mt] = (uint32_t)((m_base + mt * 16 + (quad & 1) * 8 + id8) * RSTR + ((quad >> 1) * 8) * 2);
#pragma unroll
    for (int np = 0; np < 2; np++)
        boff[np] = (uint32_t)((n_base + np * 16 + (quad >> 1) * 8 + id8) * RSTR + ((quad & 1) * 8) * 2);

    float d[4][4][4];
#pragma unroll
    for (int mt = 0; mt < 4; mt++)
#pragma unroll
        for (int nt = 0; nt < 4; nt++)
#pragma unroll
            for (int k = 0; k < 4; k++) d[mt][nt][k] = 0.f;

    const int nk = K / BK;
    float4 breg[8];

    // prologue: chunk0 + chunk1 staged
    ldgF(breg, pBf, K, 0);
    cvt_sts1(breg, sb + 1 * TILEB);
    load_tile(sb + 0 * TILEB, Ah, K, 0);
    CP_COMMIT();
    ldgF(breg, pBf, K, BK);
    cvt_sts1(breg, sb + STG2 + 1 * TILEB);
    load_tile(sb + STG2 + 0 * TILEB, Ah, K, BK);
    CP_COMMIT();
    CP_WAIT1();
    __syncthreads();

    for (int i = 0; i < nk; i++) {
        const uint32_t st = sb + (i & 1) * STG2;
        if (i + 2 < nk) ldgF(breg, pBf, K, (i + 2) * BK);

        MMA_STAGE_1T(st);

        __syncthreads();
        if (i + 2 < nk) {
            cvt_sts1(breg, st + 1 * TILEB);
            load_tile(st + 0 * TILEB, Ah, K, (i + 2) * BK);
            CP_COMMIT();
        }
        if (i + 1 < nk) {
            if (i + 2 < nk) CP_WAIT1(); else CP_WAIT0();
            __syncthreads();
        }
    }

    // epilogue: write fp16 hs1^T AND fused q/k partial sums
    __syncthreads();
    float* red = (float*)dsm;
    const int g = lane >> 2, t2 = (lane & 3) * 2;
    const int nw = wid & 3;
#pragma unroll
    for (int mt = 0; mt < 4; mt++) {
        const int r0 = m_base + mt * 16 + g;
        const int r1 = r0 + 8;
        const float bv0 = bias[r0];
        const float bv1 = bias[r1];
        const size_t base0 = (size_t)bz * o_bstr + (size_t)r0 * o_rstr + Boff;
        const size_t base1 = (size_t)bz * o_bstr + (size_t)r1 * o_rstr + Boff;
        float pq0 = 0.f, pk0 = 0.f, pq1 = 0.f, pk1 = 0.f;
#pragma unroll
        for (int nt = 0; nt < 4; nt++) {
            const int col = n_base + nt * 8 + t2;
            float v00 = d[mt][nt][0] + bv0, v01 = d[mt][nt][1] + bv0;
            float v10 = d[mt][nt][2] + bv1, v11 = d[mt][nt][3] + bv1;
            *(__half2*)(oh + base0 + col) = __floats2half2_rn(v00, v01);
            *(__half2*)(oh + base1 + col) = __floats2half2_rn(v10, v11);
            float wqa = g_wqm[Boff + col], wqb = g_wqm[Boff + col + 1];
            float wka = g_wkm[Boff + col], wkb = g_wkm[Boff + col + 1];
            pq0 = fmaf(v00, wqa, fmaf(v01, wqb, pq0));
            pk0 = fmaf(v00, wka, fmaf(v01, wkb, pk0));
            pq1 = fmaf(v10, wqa, fmaf(v11, wqb, pq1));
            pk1 = fmaf(v10, wka, fmaf(v11, wkb, pk1));
        }
#pragma unroll
        for (int o = 2; o > 0; o >>= 1) {
            pq0 += __shfl_down_sync(0xffffffffu, pq0, o, 4);
            pk0 += __shfl_down_sync(0xffffffffu, pk0, o, 4);
            pq1 += __shfl_down_sync(0xffffffffu, pq1, o, 4);
            pk1 += __shfl_down_sync(0xffffffffu, pk1, o, 4);
        }
        if ((lane & 3) == 0) {
            red[0 * 512 + nw * 128 + r0] = pq0; red[0 * 512 + nw * 128 + r1] = pq1;
            red[1 * 512 + nw * 128 + r0] = pk0; red[1 * 512 + nw * 128 + r1] = pk1;
        }
    }
    __syncthreads();
    if (tid < 128) {
        float q = red[tid] + red[128 + tid] + red[256 + tid] + red[384 + tid];
        float k = red[512 + tid] + red[640 + tid] + red[768 + tid] + red[896 + tid];
        const size_t o = ((size_t)bz * NCT + blockIdx.x) * NJ + tid;
        g_qp[o] = q;
        g_kp[o] = k;
    }
}

// ---------------------------------------------------------------------------
// q1/k1 from partials + A1^T hi/lo; grid (8, BB)
// ---------------------------------------------------------------------------
__global__ void k_qkA1(const float* __restrict__ adj, const float* __restrict__ alpha) {
    __shared__ float q1s[NJ], k1s[NJ];
    const int b = blockIdx.y, tid = threadIdx.x;
    if (tid < 128) {
        float q = g_bqkm[0], k = g_bqkm[1];
#pragma unroll
        for (int t = 0; t < NCT; t++) {
            q += g_qp[((size_t)b * NCT + t) * NJ + tid];
            k += g_kp[((size_t)b * NCT + t) * NJ + tid];
        }
        q1s[tid] = q; k1s[tid] = k;
    }
    __syncthreads();
    const float a = alpha[0];
    const int base = blockIdx.x * 2048;
#pragma unroll
    for (int u = 0; u < 8; u++) {
        const int idx = base + u * 256 + tid;
        const int k = idx >> 7, j = idx & 127;
        float v = adj[j * NJ + k] + tanhf(q1s[j] - k1s[k]) * a;
        __half h = __float2half_rn(v);
        __half l = __float2half_rn(v - __half2float(h));
        g_a1hi[(size_t)b * NJ * NJ + idx] = h;
        g_a1lo[(size_t)b * NJ * NJ + idx] = l;
    }
}

// ---------------------------------------------------------------------------
// GEMM2 (1-term, A = w_c1 fp32 rounded in-kernel) + fused GEMM3 + BN-stat/pool
// smem = 6 tiles: mainloop stages at tiles {0,1} and {2,3}; fused GEMM3 uses
// hs2 -> tiles {0,1}, A1 hi/lo -> tiles {2,3,4,5}.
// ---------------------------------------------------------------------------
__global__ __launch_bounds__(256, 1) void mma_gemm2f(
    const float* __restrict__ C1f,
    const __half* __restrict__ H1, long h1_bstr,
    const __half* __restrict__ A1h, const __half* __restrict__ A1l,
    int K,
    const float* __restrict__ bias,
    const float* __restrict__ w1f,
    float* __restrict__ sbc, float* __restrict__ ssbc, float* __restrict__ dotb)
{
    extern __shared__ char dsm[];
    const uint32_t sb = smem_u32(dsm);

    const int tid = threadIdx.x;
    const int wid = tid >> 5, lane = tid & 31;
    const int bz = blockIdx.z;
    const int Aoff = blockIdx.x * 128;

    const float* pAf = C1f + (size_t)Aoff * K;
    const __half* p2 = H1 + (size_t)bz * h1_bstr;
    const __half* a1h_b = A1h + (size_t)bz * NJ * NJ;
    const __half* a1l_b = A1l + (size_t)bz * NJ * NJ;

    const int m_base = (wid >> 2) * 64;
    const int n_base = (wid & 3) * 32;
    const int quad = lane >> 3, id8 = lane & 7;

    uint32_t aoff[4], boff[2];
#pragma unroll
    for (int mt = 0; mt < 4; mt++)
        aoff[mt] = (uint32_t)((m_base + mt * 16 + (quad & 1) * 8 + id8) * RSTR + ((quad >> 1) * 8) * 2);
#pragma unroll
    for (int np = 0; np < 2; np++)
        boff[np] = (uint32_t)((n_base + np * 16 + (quad >> 1) * 8 + id8) * RSTR + ((quad & 1) * 8) * 2);

    float d[4][4][4];
#pragma unroll
    for (int mt = 0; mt < 4; mt++)
#pragma unroll
        for (int nt = 0; nt < 4; nt++)
#pragma unroll
            for (int k = 0; k < 4; k++) d[mt][nt][k] = 0.f;

    const int nk = K / BK;
    float4 breg[8];

    // prologue (1-term: A rounded in-kernel to tile0, B = h1 via cp.async to tile1)
    ldgF(breg, pAf, K, 0);
    cvt_sts1(breg, sb + 0 * TILEB);
    load_tile(sb + 1 * TILEB, p2, K, 0);
    CP_COMMIT();
    ldgF(breg, pAf, K, BK);
    cvt_sts1(breg, sb + STG2 + 0 * TILEB);
    load_tile(sb + STG2 + 1 * TILEB, p2, K, BK);
    CP_COMMIT();
    CP_WAIT1();
    __syncthreads();

    for (int i = 0; i < nk; i++) {
        const uint32_t st = sb + (i & 1) * STG2;
        if (i + 2 < nk) ldgF(breg, pAf, K, (i + 2) * BK);

        MMA_STAGE_1T(st);

        __syncthreads();
        if (i + 2 < nk) {
            cvt_sts1(breg, st + 0 * TILEB);
            load_tile(st + 1 * TILEB, p2, K, (i + 2) * BK);
            CP_COMMIT();
        }
        if (i + 1 < nk) {
            if (i + 2 < nk) CP_WAIT1(); else CP_WAIT0();
            __syncthreads();
        }
    }

    // --- fused GEMM3: preload A1 hi/lo into tiles 2..5 ---
    load_tile(sb + 2 * TILEB, a1h_b, NJ, 0);
    load_tile(sb + 3 * TILEB, a1l_b, NJ, 0);
    load_tile(sb + 4 * TILEB, a1h_b, NJ, 64);
    load_tile(sb + 5 * TILEB, a1l_b, NJ, 64);
    CP_COMMIT();

    // write hs2 tile (+bias, fp16) into tiles 0,1 (j split across 2 slots)
    const int g = lane >> 2, t2 = (lane & 3) * 2;
#pragma unroll
    for (int mt = 0; mt < 4; mt++) {
        const int r0 = m_base + mt * 16 + g;
        const int r1 = r0 + 8;
        const float bv0 = bias[Aoff + r0];
        const float bv1 = bias[Aoff + r1];
#pragma unroll
        for (int nt = 0; nt < 4; nt++) {
            const int col = n_base + nt * 8 + t2;
            const uint32_t cslot = (uint32_t)(col >> 6) * TILEB;
            const uint32_t cl = (uint32_t)(col & 63) * 2;
            __half2 v0 = __floats2half2_rn(d[mt][nt][0] + bv0, d[mt][nt][1] + bv0);
            __half2 v1 = __floats2half2_rn(d[mt][nt][2] + bv1, d[mt][nt][3] + bv1);
            asm volatile("st.shared.b32 [%0], %1;"
                :: "r"(sb + cslot + (uint32_t)r0 * RSTR + cl), "r"(*(uint32_t*)&v0));
            asm volatile("st.shared.b32 [%0], %1;"
                :: "r"(sb + cslot + (uint32_t)r1 * RSTR + cl), "r"(*(uint32_t*)&v1));
        }
    }
    CP_WAIT0();
    __syncthreads();

#pragma unroll
    for (int mt = 0; mt < 4; mt++)
#pragma unroll
        for (int nt = 0; nt < 4; nt++)
#pragma unroll
            for (int k = 0; k < 4; k++) d[mt][nt][k] = 0.f;

    MMA_STAGE_SB3(sb + 0 * TILEB, sb + 2 * TILEB, sb + 3 * TILEB);
    MMA_STAGE_SB3(sb + 1 * TILEB, sb + 4 * TILEB, sb + 5 * TILEB);

    // --- fused BN-stat + pool epilogue ---
    __syncthreads();
    float* red = (float*)dsm;
    const int nw = wid & 3;
#pragma unroll
    for (int mt = 0; mt < 4; mt++) {
        float s0r = 0, ss0 = 0, dt0 = 0, s1r = 0, ss1 = 0, dt1 = 0;
#pragma unroll
        for (int nt = 0; nt < 4; nt++) {
            const int col = n_base + nt * 8 + t2;
            float wa = __ldg(w1f + col), wb = __ldg(w1f + col + 1);
            float v00 = d[mt][nt][0], v01 = d[mt][nt][1];
            float v10 = d[mt][nt][2], v11 = d[mt][nt][3];
            s0r += v00 + v01;  ss0 = fmaf(v00, v00, fmaf(v01, v01, ss0));
            dt0 = fmaf(v00, wa, fmaf(v01, wb, dt0));
            s1r += v10 + v11;  ss1 = fmaf(v10, v10, fmaf(v11, v11, ss1));
            dt1 = fmaf(v10, wa, fmaf(v11, wb, dt1));
        }
#pragma unroll
        for (int o = 2; o > 0; o >>= 1) {
            s0r += __shfl_down_sync(0xffffffffu, s0r, o, 4);
            ss0 += __shfl_down_sync(0xffffffffu, ss0, o, 4);
            dt0 += __shfl_down_sync(0xffffffffu, dt0, o, 4);
            s1r += __shfl_down_sync(0xffffffffu, s1r, o, 4);
            ss1 += __shfl_down_sync(0xffffffffu, ss1, o, 4);
            dt1 += __shfl_down_sync(0xffffffffu, dt1, o, 4);
        }
        if ((lane & 3) == 0) {
            const int r0 = m_base + mt * 16 + g, r1 = r0 + 8;
            red[0 * 512 + nw * 128 + r0] = s0r; red[0 * 512 + nw * 128 + r1] = s1r;
            red[1 * 512 + nw * 128 + r0] = ss0; red[1 * 512 + nw * 128 + r1] = ss1;
            red[2 * 512 + nw * 128 + r0] = dt0; red[2 * 512 + nw * 128 + r1] = dt1;
        }
    }
    __syncthreads();
    if (tid < 128) {
        float s  = red[tid] + red[128 + tid] + red[256 + tid] + red[384 + tid];
        float ss = red[512 + tid] + red[640 + tid] + red[768 + tid] + red[896 + tid];
        float dt = red[1024 + tid] + red[1152 + tid] + red[1280 + tid] + red[1408 + tid];
        const size_t o = (size_t)bz * PS + Aoff + tid;
        sbc[o] = s; ssbc[o] = ss; dotb[o] = dt;
    }
}

// ---------------------------------------------------------------------------
// small kernels
// ---------------------------------------------------------------------------
__global__ void k_wmeans(const float* __restrict__ wq, const float* __restrict__ wk,
                         const float* __restrict__ bq, const float* __restrict__ bk) {
    const int bx = blockIdx.x;
    if (bx < 48) {
        const int tx = threadIdx.x & 31, ty = threadIdx.x >> 5;
        const int c = bx * 32 + tx;
        float sq = 0.f, sk = 0.f;
        for (int o = ty; o < QK; o += 8) {
            sq += wq[(size_t)o * PS + c];
            sk += wk[(size_t)o * PS + c];
        }
        __shared__ float aq[8][32], ak[8][32];
        aq[ty][tx] = sq; ak[ty][tx] = sk;
        __syncthreads();
        if (ty == 0) {
#pragma unroll
            for (int u = 1; u < 8; u++) { sq += aq[u][tx]; sk += ak[u][tx]; }
            g_wqm[c] = sq * (1.0f / QK);
            g_wkm[c] = sk * (1.0f / QK);
        }
    } else if (threadIdx.x < 32) {
        const float* src = (bx == 48) ? bq : bk;
        float s = 0.f;
        for (int o = threadIdx.x; o < QK; o += 32) s += src[o];
#pragma unroll
        for (int o = 16; o > 0; o >>= 1) s += __shfl_down_sync(0xffffffffu, s, o);
        if (threadIdx.x == 0) g_bqkm[bx - 48] = s * (1.0f / QK);
    }
}

// hs4: block (32 b-lanes, 8 c), grid PS/8 = 192
__global__ void k_hs4(const float* __restrict__ gamma, const float* __restrict__ beta,
                      const float* __restrict__ w1, const float* __restrict__ b1) {
    __shared__ float sws;
    const int tid = threadIdx.y * 32 + threadIdx.x;
    if (tid < 32) {
        float sw = 0.f;
#pragma unroll
        for (int j = tid; j < NJ; j += 32) sw += w1[j];
#pragma unroll
        for (int o = 16; o > 0; o >>= 1) sw += __shfl_down_sync(0xffffffffu, sw, o);
        if (tid == 0) sws = sw;
    }
    __syncthreads();
    const float sw = sws;
    const int c = blockIdx.x * 8 + threadIdx.y;
    const int b = threadIdx.x;
    const size_t o = (size_t)b * PS + c;
    float st  = g_sbc[o];
    float sst = g_ssbc[o];
#pragma unroll
    for (int u = 16; u > 0; u >>= 1) {
        st  += __shfl_down_sync(0xffffffffu, st, u);
        sst += __shfl_down_sync(0xffffffffu, sst, u);
    }
    st  = __shfl_sync(0xffffffffu, st, 0);
    sst = __shfl_sync(0xffffffffu, sst, 0);
    const float inv = 1.0f / (BB * NJ);
    float mean = st * inv;
    float var = sst * inv - mean * mean;
    float rstd = rsqrtf(var + 1e-5f);
    float ga = gamma[c] * rstd;
    float be = beta[c] * sw + b1[0];
    float msw = mean * sw;
    g_hs4[b * PS + c] = ga * (g_dotb[o] - msw) + be;
}

__global__ void k_cls(const float* __restrict__ wcls, const float* __restrict__ bcls,
                      float* __restrict__ out) {
    __shared__ __align__(16) float sh[PS];
    const int b = blockIdx.x;
    for (int i = threadIdx.x; i < PS; i += blockDim.x) sh[i] = g_hs4[b * PS + i];
    __syncthreads();
    const int n = threadIdx.x;
    if (n < NC) {
        float acc = bcls[n];
        const float4* w4 = (const float4*)(wcls + (size_t)n * PS);
        const float4* s4 = (const float4*)sh;
        for (int c = 0; c < PS / 4; c++) {
            float4 w = w4[c], s = s4[c];
            acc = fmaf(s.x, w.x, acc);
            acc = fmaf(s.y, w.y, acc);
            acc = fmaf(s.z, w.z, acc);
            acc = fmaf(s.w, w.w, acc);
        }
        out[b * NC + n] = acc;
    }
}

// ---------------------------------------------------------------------------
// launch
// ---------------------------------------------------------------------------
extern "C" void kernel_launch(void* const* d_in, const int* in_sizes, int n_in,
                              void* d_out, int out_size) {
    (void)in_sizes; (void)n_in; (void)out_size;
    const float* x       = (const float*)d_in[0];
    const float* w_pool0 = (const float*)d_in[1];
    const float* b_pool0 = (const float*)d_in[2];
    const float* adj1    = (const float*)d_in[3];
    const float* w_q     = (const float*)d_in[4];
    const float* b_q     = (const float*)d_in[5];
    const float* w_k     = (const float*)d_in[6];
    const float* b_k     = (const float*)d_in[7];
    const float* alpha   = (const float*)d_in[8];
    const float* w_c1    = (const float*)d_in[9];
    const float* b_c1    = (const float*)d_in[10];
    const float* gamma   = (const float*)d_in[11];
    const float* beta    = (const float*)d_in[12];
    const float* w_pool1 = (const float*)d_in[13];
    const float* b_pool1 = (const float*)d_in[14];
    const float* w_cls   = (const float*)d_in[15];
    const float* b_cls   = (const float*)d_in[16];
    float* out = (float*)d_out;

    __half *w0h, *h1, *a1hi, *a1lo;
    float *sbc, *ssbc, *dotb;
    cudaGetSymbolAddress((void**)&w0h,  g_w0h);
    cudaGetSymbolAddress((void**)&h1,   g_h1);
    cudaGetSymbolAddress((void**)&a1hi, g_a1hi);
    cudaGetSymbolAddress((void**)&a1lo, g_a1lo);
    cudaGetSymbolAddress((void**)&sbc,  g_sbc);
    cudaGetSymbolAddress((void**)&ssbc, g_ssbc);
    cudaGetSymbolAddress((void**)&dotb, g_dotb);

    const int smem_x  = 2 * STG2;   // 73728
    const int smem_2f = 6 * TILEB;  // 110592 (mainloop 2x2 tiles + fused GEMM3 slots)
    cudaFuncSetAttribute(mma_gemm2f, cudaFuncAttributeMaxDynamicSharedMemorySize, smem_2f);
    cudaFuncSetAttribute(mma_gemm_x, cudaFuncAttributeMaxDynamicSharedMemorySize, smem_x);

    // w0 fp16 round + q/k weight means
    k_cvt_w0<<<(unsigned)((long)NJ * TNS / 4 / 256), 256>>>(w_pool0);
    k_wmeans<<<50, 256>>>(w_q, w_k, b_q, b_k);

    // GEMM1 (1-term) + fused q/k partials
    mma_gemm_x<<<dim3(NCT, 1, BB), 256, smem_x>>>(
        w0h,
        x, (long)PS * TNS,
        TNS, b_pool0,
        h1, (long)NJ * PS, PS);

    // q1/k1 reduce + A1^T build
    k_qkA1<<<dim3(8, BB), 256>>>(adj1, alpha);

    // GEMM2 (1-term, inline c1 round) + fused GEMM3 + fused BN-stat/pool
    mma_gemm2f<<<dim3(NCT, 1, BB), 256, smem_2f>>>(
        w_c1,
        h1, (long)NJ * PS,
        a1hi, a1lo,
        PS, b_c1,
        w_pool1, sbc, ssbc, dotb);

    k_hs4<<<PS / 8, dim3(32, 8)>>>(gamma, beta, w_pool1, b_pool1);
    k_cls<<<BB, 256>>>(w_cls, b_cls, out);
}

// round 16
// speedup vs baseline: 1.4698x; 1.0283x over previous
#include <cuda_runtime.h>
#include <cuda_fp16.h>
#include <cstdint>
#include <cstddef>

#define BB   32
#define PS   1536
#define TNS  2048
#define NJ   128
#define QK   384
#define NC   200
#define NCT  12          // c-tiles per batch in GEMM1

// ---------------------------------------------------------------------------
// scratch (static device globals; no allocation)
// ---------------------------------------------------------------------------
__device__ __half g_w0h [(size_t)NJ * TNS];       // w0 rounded fp16
__device__ __half g_h1  [(size_t)BB * NJ * PS];   // hs1^T [b][j][c], fp16
__device__ __half g_a1hi[(size_t)BB * NJ * NJ];   // A1^T  [b][k][j]
__device__ __half g_a1lo[(size_t)BB * NJ * NJ];
__device__ float g_qp  [(size_t)BB * NCT * NJ];
__device__ float g_kp  [(size_t)BB * NCT * NJ];
__device__ float g_sbc [(size_t)BB * PS];
__device__ float g_ssbc[(size_t)BB * PS];
__device__ float g_dotb[(size_t)BB * PS];
__device__ float g_wqm[PS];
__device__ float g_wkm[PS];
__device__ float g_bqkm[2];
__device__ float g_hs4[BB * PS];

// ---------------------------------------------------------------------------
// helpers
// ---------------------------------------------------------------------------
__device__ __forceinline__ uint32_t smem_u32(const void* p) {
    uint32_t a;
    asm("{ .reg .u64 t; cvta.to.shared.u64 t, %1; cvt.u32.u64 %0, t; }" : "=r"(a) : "l"(p));
    return a;
}
#define CP_COMMIT() asm volatile("cp.async.commit_group;" ::: "memory")
#define CP_WAIT0()  asm volatile("cp.async.wait_group 0;" ::: "memory")
#define CP_WAIT1()  asm volatile("cp.async.wait_group 1;" ::: "memory")

__device__ __forceinline__ void ld4(uint32_t* r, uint32_t a) {
    asm volatile("ldmatrix.sync.aligned.m8n8.x4.shared.b16 {%0,%1,%2,%3}, [%4];"
        : "=r"(r[0]), "=r"(r[1]), "=r"(r[2]), "=r"(r[3]) : "r"(a));
}
__device__ __forceinline__ void mma16816(float* d, const uint32_t* a, const uint32_t* b) {
    asm volatile(
        "mma.sync.aligned.m16n8k16.row.col.f32.f16.f16.f32 "
        "{%0,%1,%2,%3}, {%4,%5,%6,%7}, {%8,%9}, {%0,%1,%2,%3};"
        : "+f"(d[0]), "+f"(d[1]), "+f"(d[2]), "+f"(d[3])
        : "r"(a[0]), "r"(a[1]), "r"(a[2]), "r"(a[3]), "r"(b[0]), "r"(b[1]));
}

// fp32 -> fp16 round for w0
__global__ void k_cvt_w0(const float* __restrict__ s) {
    long i = (long)blockIdx.x * blockDim.x + threadIdx.x;
    float4 v = ((const float4*)s)[i];
    __half2 h01 = __floats2half2_rn(v.x, v.y);
    __half2 h23 = __floats2half2_rn(v.z, v.w);
    ((__half2*)g_w0h)[i * 2 + 0] = h01;
    ((__half2*)g_w0h)[i * 2 + 1] = h23;
}

// ---------------------------------------------------------------------------
// SMEM tile: 128 rows x 128 k fp16, 256B/row + 16 pad (272B = 68 banks == 4 mod 32)
// ---------------------------------------------------------------------------
#define BK    128
#define RSTR  272
#define TILEB (128 * RSTR)     // 34816
#define STG2  (2 * TILEB)      // mainloop stage (A, B)

__device__ __forceinline__ void load_tile(uint32_t sb, const __half* g, int gstride, int k0) {
    const int t = threadIdx.x;
#pragma unroll
    for (int p = 0; p < 8; p++) {
        int idx = p * 256 + t;
        int row = idx >> 4, ch = idx & 15;
        uint32_t dst = sb + row * RSTR + ch * 16;
        const void* src = g + (size_t)row * gstride + k0 + ch * 8;
        asm volatile("cp.async.cg.shared.global [%0], [%1], 16;" :: "r"(dst), "l"(src));
    }
}

// 1-term MMA over one stage (8 k16 steps): tile0 = A, tile1 = B
#define MMA_STAGE_1T(st)                                                         \
    do {                                                                         \
        _Pragma("unroll")                                                        \
        for (int ks = 0; ks < 8; ks++) {                                         \
            const uint32_t klo = ks * 32;                                        \
            uint32_t ah[4][4], bf[2][4];                                         \
            _Pragma("unroll")                                                    \
            for (int mt = 0; mt < 4; mt++) ld4(ah[mt], (st) + 0 * TILEB + aoff[mt] + klo); \
            _Pragma("unroll")                                                    \
            for (int np = 0; np < 2; np++) ld4(bf[np], (st) + 1 * TILEB + boff[np] + klo); \
            _Pragma("unroll")                                                    \
            for (int mt = 0; mt < 4; mt++)                                       \
                _Pragma("unroll")                                                \
                for (int nt = 0; nt < 4; nt++)                                   \
                    mma16816(d[mt][nt], ah[mt], &bf[nt >> 1][(nt & 1) * 2]);     \
        }                                                                        \
    } while (0)

// 2-term MMA over one 128-k chunk, explicit slots: A single, B hi/lo (fused GEMM3)
#define MMA_STAGE_SB3(sA, sBh, sBl)                                              \
    do {                                                                         \
        _Pragma("unroll")                                                        \
        for (int ks = 0; ks < 8; ks++) {                                         \
            const uint32_t klo = ks * 32;                                        \
            uint32_t af[4][4], bh[2][4];                                         \
            _Pragma("unroll")                                                    \
            for (int mt = 0; mt < 4; mt++) ld4(af[mt], (sA) + aoff[mt] + klo);   \
            _Pragma("unroll")                                                    \
            for (int np = 0; np < 2; np++) ld4(bh[np], (sBh) + boff[np] + klo);  \
            _Pragma("unroll")                                                    \
            for (int mt = 0; mt < 4; mt++)                                       \
                _Pragma("unroll")                                                \
                for (int nt = 0; nt < 4; nt++)                                   \
                    mma16816(d[mt][nt], af[mt], &bh[nt >> 1][(nt & 1) * 2]);     \
            {                                                                    \
                uint32_t bl[2][4];                                               \
                _Pragma("unroll")                                                \
                for (int np = 0; np < 2; np++) ld4(bl[np], (sBl) + boff[np] + klo); \
                _Pragma("unroll")                                                \
                for (int mt = 0; mt < 4; mt++)                                   \
                    _Pragma("unroll")                                            \
                    for (int nt = 0; nt < 4; nt++)                               \
                        mma16816(d[mt][nt], af[mt], &bl[nt >> 1][(nt & 1) * 2]); \
            }                                                                    \
        }                                                                        \
    } while (0)

// fp32 LDG of a 128x64 half-chunk into registers (8 x float4 per thread)
__device__ __forceinline__ void ldgF(float4* br, const float* pB, int K, int k0) {
    const int t = threadIdx.x;
#pragma unroll
    for (int p = 0; p < 8; p++) {
        int idx = p * 256 + t;
        int row = idx >> 4, f4 = idx & 15;
        br[p] = *(const float4*)(pB + (size_t)row * K + k0 + f4 * 4);
    }
}
// fp16-round STS of a 64-col half into one tile slot at byte offset kb
__device__ __forceinline__ void cvt_sts1(const float4* br, uint32_t slot, uint32_t kb) {
    const int t = threadIdx.x;
#pragma unroll
    for (int p = 0; p < 8; p++) {
        int idx = p * 256 + t;
        int row = idx >> 4, f4 = idx & 15;
        float4 v = br[p];
        __half2 h01 = __floats2half2_rn(v.x, v.y);
        __half2 h23 = __floats2half2_rn(v.z, v.w);
        uint32_t off = (uint32_t)(row * RSTR + kb + f4 * 8);
        asm volatile("st.shared.v2.b32 [%0], {%1,%2};"
            :: "r"(slot + off), "r"(*(uint32_t*)&h01), "r"(*(uint32_t*)&h23));
    }
}

// ---------------------------------------------------------------------------
// GEMM1 (1-term): hs1^T[j, c-tile] = w0_fp16[j,:] . x_fp16[b, c,:] + fused q/k partials
// tile0 = w0 (cp.async), tile1 = x (ldg+round)
// ---------------------------------------------------------------------------
__global__ __launch_bounds__(256, 1) void mma_gemm_x(
    const __half* __restrict__ Ah,
    const float* __restrict__ Bf, long b_bstr,
    int K,
    const float* __restrict__ bias,
    __half* __restrict__ oh,
    long o_bstr, int o_rstr)
{
    extern __shared__ char dsm[];
    const uint32_t sb = smem_u32(dsm);

    const int tid = threadIdx.x;
    const int wid = tid >> 5, lane = tid & 31;
    const int bz = blockIdx.z;
    const int Boff = blockIdx.x * 128;
    const float* pBf = Bf + (size_t)bz * b_bstr + (size_t)Boff * K;

    const int m_base = (wid >> 2) * 64;
    const int n_base = (wid & 3) * 32;
    const int quad = lane >> 3, id8 = lane & 7;

    uint32_t aoff[4], boff[2];
#pragma unroll
    for (int mt = 0; mt < 4; mt++)
        aoff[mt] = (uint32_t)((m_base + mt * 16 + (quad & 1) * 8 + id8) * RSTR + ((quad >> 1) * 8) * 2);
#pragma unroll
    for (int np = 0; np < 2; np++)
        boff[np] = (uint32_t)((n_base + np * 16 + (quad >> 1) * 8 + id8) * RSTR + ((quad & 1) * 8) * 2);

    float d[4][4][4];
#pragma unroll
    for (int mt = 0; mt < 4; mt++)
#pragma unroll
        for (int nt = 0; nt < 4; nt++)
#pragma unroll
            for (int k = 0; k < 4; k++) d[mt][nt][k] = 0.f;

    const int nk = K / BK;   // 16
    float4 br0[8], br1[8];

    // prologue: chunk0 + chunk1 staged
    ldgF(br0, pBf, K, 0);
    ldgF(br1, pBf, K, 64);
    cvt_sts1(br0, sb + 1 * TILEB, 0);
    cvt_sts1(br1, sb + 1 * TILEB, 128);
    load_tile(sb + 0 * TILEB, Ah, K, 0);
    CP_COMMIT();
    ldgF(br0, pBf, K, BK);
    ldgF(br1, pBf, K, BK + 64);
    cvt_sts1(br0, sb + STG2 + 1 * TILEB, 0);
    cvt_sts1(br1, sb + STG2 + 1 * TILEB, 128);
    load_tile(sb + STG2 + 0 * TILEB, Ah, K, BK);
    CP_COMMIT();
    CP_WAIT1();
    __syncthreads();

    for (int i = 0; i < nk; i++) {
        const uint32_t st = sb + (i & 1) * STG2;
        if (i + 2 < nk) {
            ldgF(br0, pBf, K, (i + 2) * BK);
            ldgF(br1, pBf, K, (i + 2) * BK + 64);
        }

        MMA_STAGE_1T(st);

        __syncthreads();
        if (i + 2 < nk) {
            cvt_sts1(br0, st + 1 * TILEB, 0);
            cvt_sts1(br1, st + 1 * TILEB, 128);
            load_tile(st + 0 * TILEB, Ah, K, (i + 2) * BK);
            CP_COMMIT();
        }
        if (i + 1 < nk) {
            if (i + 2 < nk) CP_WAIT1(); else CP_WAIT0();
            __syncthreads();
        }
    }

    // epilogue: write fp16 hs1^T AND fused q/k partial sums
    __syncthreads();
    float* red = (float*)dsm;
    const int g = lane >> 2, t2 = (lane & 3) * 2;
    const int nw = wid & 3;
#pragma unroll
    for (int mt = 0; mt < 4; mt++) {
        const int r0 = m_base + mt * 16 + g;
        const int r1 = r0 + 8;
        const float bv0 = bias[r0];
        const float bv1 = bias[r1];
        const size_t base0 = (size_t)bz * o_bstr + (size_t)r0 * o_rstr + Boff;
        const size_t base1 = (size_t)bz * o_bstr + (size_t)r1 * o_rstr + Boff;
        float pq0 = 0.f, pk0 = 0.f, pq1 = 0.f, pk1 = 0.f;
#pragma unroll
        for (int nt = 0; nt < 4; nt++) {
            const int col = n_base + nt * 8 + t2;
            float v00 = d[mt][nt][0] + bv0, v01 = d[mt][nt][1] + bv0;
            float v10 = d[mt][nt][2] + bv1, v11 = d[mt][nt][3] + bv1;
            *(__half2*)(oh + base0 + col) = __floats2half2_rn(v00, v01);
            *(__half2*)(oh + base1 + col) = __floats2half2_rn(v10, v11);
            float wqa = g_wqm[Boff + col], wqb = g_wqm[Boff + col + 1];
            float wka = g_wkm[Boff + col], wkb = g_wkm[Boff + col + 1];
            pq0 = fmaf(v00, wqa, fmaf(v01, wqb, pq0));
            pk0 = fmaf(v00, wka, fmaf(v01, wkb, pk0));
            pq1 = fmaf(v10, wqa, fmaf(v11, wqb, pq1));
            pk1 = fmaf(v10, wka, fmaf(v11, wkb, pk1));
        }
#pragma unroll
        for (int o = 2; o > 0; o >>= 1) {
            pq0 += __shfl_down_sync(0xffffffffu, pq0, o, 4);
            pk0 += __shfl_down_sync(0xffffffffu, pk0, o, 4);
            pq1 += __shfl_down_sync(0xffffffffu, pq1, o, 4);
            pk1 += __shfl_down_sync(0xffffffffu, pk1, o, 4);
        }
        if ((lane & 3) == 0) {
            red[0 * 512 + nw * 128 + r0] = pq0; red[0 * 512 + nw * 128 + r1] = pq1;
            red[1 * 512 + nw * 128 + r0] = pk0; red[1 * 512 + nw * 128 + r1] = pk1;
        }
    }
    __syncthreads();
    if (tid < 128) {
        float q = red[tid] + red[128 + tid] + red[256 + tid] + red[384 + tid];
        float k = red[512 + tid] + red[640 + tid] + red[768 + tid] + red[896 + tid];
        const size_t o = ((size_t)bz * NCT + blockIdx.x) * NJ + tid;
        g_qp[o] = q;
        g_kp[o] = k;
    }
}

// ---------------------------------------------------------------------------
// q1/k1 from partials + A1^T hi/lo; grid (8, BB)
// ---------------------------------------------------------------------------
__global__ void k_qkA1(const float* __restrict__ adj, const float* __restrict__ alpha) {
    __shared__ float q1s[NJ], k1s[NJ];
    const int b = blockIdx.y, tid = threadIdx.x;
    if (tid < 128) {
        float q = g_bqkm[0], k = g_bqkm[1];
#pragma unroll
        for (int t = 0; t < NCT; t++) {
            q += g_qp[((size_t)b * NCT + t) * NJ + tid];
            k += g_kp[((size_t)b * NCT + t) * NJ + tid];
        }
        q1s[tid] = q; k1s[tid] = k;
    }
    __syncthreads();
    const float a = alpha[0];
    const int base = blockIdx.x * 2048;
#pragma unroll
    for (int u = 0; u < 8; u++) {
        const int idx = base + u * 256 + tid;
        const int k = idx >> 7, j = idx & 127;
        float v = adj[j * NJ + k] + tanhf(q1s[j] - k1s[k]) * a;
        __half h = __float2half_rn(v);
        __half l = __float2half_rn(v - __half2float(h));
        g_a1hi[(size_t)b * NJ * NJ + idx] = h;
        g_a1lo[(size_t)b * NJ * NJ + idx] = l;
    }
}

// ---------------------------------------------------------------------------
// GEMM2 (1-term, A = w_c1 fp32 rounded in-kernel) + fused GEMM3 + BN-stat/pool
// smem = 4 tiles: mainloop stages {0,1} and {2,3}.
// Fused GEMM3 (K = 128 = one chunk): hs2 -> tile0, A1h -> tile1, A1l -> tile2.
// ---------------------------------------------------------------------------
__global__ __launch_bounds__(256, 1) void mma_gemm2f(
    const float* __restrict__ C1f,
    const __half* __restrict__ H1, long h1_bstr,
    const __half* __restrict__ A1h, const __half* __restrict__ A1l,
    int K,
    const float* __restrict__ bias,
    const float* __restrict__ w1f,
    float* __restrict__ sbc, float* __restrict__ ssbc, float* __restrict__ dotb)
{
    extern __shared__ char dsm[];
    const uint32_t sb = smem_u32(dsm);

    const int tid = threadIdx.x;
    const int wid = tid >> 5, lane = tid & 31;
    const int bz = blockIdx.z;
    const int Aoff = blockIdx.x * 128;

    const float* pAf = C1f + (size_t)Aoff * K;
    const __half* p2 = H1 + (size_t)bz * h1_bstr;
    const __half* a1h_b = A1h + (size_t)bz * NJ * NJ;
    const __half* a1l_b = A1l + (size_t)bz * NJ * NJ;

    const int m_base = (wid >> 2) * 64;
    const int n_base = (wid & 3) * 32;
    const int quad = lane >> 3, id8 = lane & 7;

    uint32_t aoff[4], boff[2];
#pragma unroll
    for (int mt = 0; mt < 4; mt++)
        aoff[mt] = (uint32_t)((m_base + mt * 16 + (quad & 1) * 8 + id8) * RSTR + ((quad >> 1) * 8) * 2);
#pragma unroll
    for (int np = 0; np < 2; np++)
        boff[np] = (uint32_t)((n_base + np * 16 + (quad >> 1) * 8 + id8) * RSTR + ((quad & 1) * 8) * 2);

    float d[4][4][4];
#pragma unroll
    for (int mt = 0; mt < 4; mt++)
#pragma unroll
        for (int nt = 0; nt < 4; nt++)
#pragma unroll
            for (int k = 0; k < 4; k++) d[mt][nt][k] = 0.f;

    const int nk = K / BK;   // 12
    float4 br0[8], br1[8];

    // prologue: A = c1 (ldg+round into tile0), B = h1 (cp.async into tile1)
    ldgF(br0, pAf, K, 0);
    ldgF(br1, pAf, K, 64);
    cvt_sts1(br0, sb + 0 * TILEB, 0);
    cvt_sts1(br1, sb + 0 * TILEB, 128);
    load_tile(sb + 1 * TILEB, p2, K, 0);
    CP_COMMIT();
    ldgF(br0, pAf, K, BK);
    ldgF(br1, pAf, K, BK + 64);
    cvt_sts1(br0, sb + STG2 + 0 * TILEB, 0);
    cvt_sts1(br1, sb + STG2 + 0 * TILEB, 128);
    load_tile(sb + STG2 + 1 * TILEB, p2, K, BK);
    CP_COMMIT();
    CP_WAIT1();
    __syncthreads();

    for (int i = 0; i < nk; i++) {
        const uint32_t st = sb + (i & 1) * STG2;
        if (i + 2 < nk) {
            ldgF(br0, pAf, K, (i + 2) * BK);
            ldgF(br1, pAf, K, (i + 2) * BK + 64);
        }

        MMA_STAGE_1T(st);

        __syncthreads();
        if (i + 2 < nk) {
            cvt_sts1(br0, st + 0 * TILEB, 0);
            cvt_sts1(br1, st + 0 * TILEB, 128);
            load_tile(st + 1 * TILEB, p2, K, (i + 2) * BK);
            CP_COMMIT();
        }
        if (i + 1 < nk) {
            if (i + 2 < nk) CP_WAIT1(); else CP_WAIT0();
            __syncthreads();
        }
    }
    // all MMAs done (loop body syncs after MMA) — tiles free

    // --- fused GEMM3: A1 hi/lo -> tiles 1,2 via cp.async; hs2 -> tile0 ---
    load_tile(sb + 1 * TILEB, a1h_b, NJ, 0);
    load_tile(sb + 2 * TILEB, a1l_b, NJ, 0);
    CP_COMMIT();

    const int g = lane >> 2, t2 = (lane & 3) * 2;
#pragma unroll
    for (int mt = 0; mt < 4; mt++) {
        const int r0 = m_base + mt * 16 + g;
        const int r1 = r0 + 8;
        const float bv0 = bias[Aoff + r0];
        const float bv1 = bias[Aoff + r1];
#pragma unroll
        for (int nt = 0; nt < 4; nt++) {
            const int col = n_base + nt * 8 + t2;
            __half2 v0 = __floats2half2_rn(d[mt][nt][0] + bv0, d[mt][nt][1] + bv0);
            __half2 v1 = __floats2half2_rn(d[mt][nt][2] + bv1, d[mt][nt][3] + bv1);
            asm volatile("st.shared.b32 [%0], %1;"
                :: "r"(sb + (uint32_t)r0 * RSTR + (uint32_t)col * 2), "r"(*(uint32_t*)&v0));
            asm volatile("st.shared.b32 [%0], %1;"
                :: "r"(sb + (uint32_t)r1 * RSTR + (uint32_t)col * 2), "r"(*(uint32_t*)&v1));
        }
    }
    CP_WAIT0();
    __syncthreads();

#pragma unroll
    for (int mt = 0; mt < 4; mt++)
#pragma unroll
        for (int nt = 0; nt < 4; nt++)
#pragma unroll
            for (int k = 0; k < 4; k++) d[mt][nt][k] = 0.f;

    MMA_STAGE_SB3(sb + 0 * TILEB, sb + 1 * TILEB, sb + 2 * TILEB);

    // --- fused BN-stat + pool epilogue ---
    __syncthreads();
    float* red = (float*)dsm;
    const int nw = wid & 3;
#pragma unroll
    for (int mt = 0; mt < 4; mt++) {
        float s0r = 0, ss0 = 0, dt0 = 0, s1r = 0, ss1 = 0, dt1 = 0;
#pragma unroll
        for (int nt = 0; nt < 4; nt++) {
            const int col = n_base + nt * 8 + t2;
            float wa = __ldg(w1f + col), wb = __ldg(w1f + col + 1);
            float v00 = d[mt][nt][0], v01 = d[mt][nt][1];
            float v10 = d[mt][nt][2], v11 = d[mt][nt][3];
            s0r += v00 + v01;  ss0 = fmaf(v00, v00, fmaf(v01, v01, ss0));
            dt0 = fmaf(v00, wa, fmaf(v01, wb, dt0));
            s1r += v10 + v11;  ss1 = fmaf(v10, v10, fmaf(v11, v11, ss1));
            dt1 = fmaf(v10, wa, fmaf(v11, wb, dt1));
        }
#pragma unroll
        for (int o = 2; o > 0; o >>= 1) {
            s0r += __shfl_down_sync(0xffffffffu, s0r, o, 4);
            ss0 += __shfl_down_sync(0xffffffffu, ss0, o, 4);
            dt0 += __shfl_down_sync(0xffffffffu, dt0, o, 4);
            s1r += __shfl_down_sync(0xffffffffu, s1r, o, 4);
            ss1 += __shfl_down_sync(0xffffffffu, ss1, o, 4);
            dt1 += __shfl_down_sync(0xffffffffu, dt1, o, 4);
        }
        if ((lane & 3) == 0) {
            const int r0 = m_base + mt * 16 + g, r1 = r0 + 8;
            red[0 * 512 + nw * 128 + r0] = s0r; red[0 * 512 + nw * 128 + r1] = s1r;
            red[1 * 512 + nw * 128 + r0] = ss0; red[1 * 512 + nw * 128 + r1] = ss1;
            red[2 * 512 + nw * 128 + r0] = dt0; red[2 * 512 + nw * 128 + r1] = dt1;
        }
    }
    __syncthreads();
    if (tid < 128) {
        float s  = red[tid] + red[128 + tid] + red[256 + tid] + red[384 + tid];
        float ss = red[512 + tid] + red[640 + tid] + red[768 + tid] + red[896 + tid];
        float dt = red[1024 + tid] + red[1152 + tid] + red[1280 + tid] + red[1408 + tid];
        const size_t o = (size_t)bz * PS + Aoff + tid;
        sbc[o] = s; ssbc[o] = ss; dotb[o] = dt;
    }
}

// ---------------------------------------------------------------------------
// small kernels
// ---------------------------------------------------------------------------
__global__ void k_wmeans(const float* __restrict__ wq, const float* __restrict__ wk,
                         const float* __restrict__ bq, const float* __restrict__ bk) {
    const int bx = blockIdx.x;
    if (bx < 48) {
        const int tx = threadIdx.x & 31, ty = threadIdx.x >> 5;
        const int c = bx * 32 + tx;
        float sq = 0.f, sk = 0.f;
        for (int o = ty; o < QK; o += 8) {
            sq += wq[(size_t)o * PS + c];
            sk += wk[(size_t)o * PS + c];
        }
        __shared__ float aq[8][32], ak[8][32];
        aq[ty][tx] = sq; ak[ty][tx] = sk;
        __syncthreads();
        if (ty == 0) {
#pragma unroll
            for (int u = 1; u < 8; u++) { sq += aq[u][tx]; sk += ak[u][tx]; }
            g_wqm[c] = sq * (1.0f / QK);
            g_wkm[c] = sk * (1.0f / QK);
        }
    } else if (threadIdx.x < 32) {
        const float* src = (bx == 48) ? bq : bk;
        float s = 0.f;
        for (int o = threadIdx.x; o < QK; o += 32) s += src[o];
#pragma unroll
        for (int o = 16; o > 0; o >>= 1) s += __shfl_down_sync(0xffffffffu, s, o);
        if (threadIdx.x == 0) g_bqkm[bx - 48] = s * (1.0f / QK);
    }
}

// hs4: block (32 b-lanes, 8 c), grid PS/8 = 192
__global__ void k_hs4(const float* __restrict__ gamma, const float* __restrict__ beta,
                      const float* __restrict__ w1, const float* __restrict__ b1) {
    __shared__ float sws;
    const int tid = threadIdx.y * 32 + threadIdx.x;
    if (tid < 32) {
        float sw = 0.f;
#pragma unroll
        for (int j = tid; j < NJ; j += 32) sw += w1[j];
#pragma unroll
        for (int o = 16; o > 0; o >>= 1) sw += __shfl_down_sync(0xffffffffu, sw, o);
        if (tid == 0) sws = sw;
    }
    __syncthreads();
    const float sw = sws;
    const int c = blockIdx.x * 8 + threadIdx.y;
    const int b = threadIdx.x;
    const size_t o = (size_t)b * PS + c;
    float st  = g_sbc[o];
    float sst = g_ssbc[o];
#pragma unroll
    for (int u = 16; u > 0; u >>= 1) {
        st  += __shfl_down_sync(0xffffffffu, st, u);
        sst += __shfl_down_sync(0xffffffffu, sst, u);
    }
    st  = __shfl_sync(0xffffffffu, st, 0);
    sst = __shfl_sync(0xffffffffu, sst, 0);
    const float inv = 1.0f / (BB * NJ);
    float mean = st * inv;
    float var = sst * inv - mean * mean;
    float rstd = rsqrtf(var + 1e-5f);
    float ga = gamma[c] * rstd;
    float be = beta[c] * sw + b1[0];
    float msw = mean * sw;
    g_hs4[b * PS + c] = ga * (g_dotb[o] - msw) + be;
}

__global__ void k_cls(const float* __restrict__ wcls, const float* __restrict__ bcls,
                      float* __restrict__ out) {
    __shared__ __align__(16) float sh[PS];
    const int b = blockIdx.x;
    for (int i = threadIdx.x; i < PS; i += blockDim.x) sh[i] = g_hs4[b * PS + i];
    __syncthreads();
    const int n = threadIdx.x;
    if (n < NC) {
        float acc = bcls[n];
        const float4* w4 = (const float4*)(wcls + (size_t)n * PS);
        const float4* s4 = (const float4*)sh;
        for (int c = 0; c < PS / 4; c++) {
            float4 w = w4[c], s = s4[c];
            acc = fmaf(s.x, w.x, acc);
            acc = fmaf(s.y, w.y, acc);
            acc = fmaf(s.z, w.z, acc);
            acc = fmaf(s.w, w.w, acc);
        }
        out[b * NC + n] = acc;
    }
}

// ---------------------------------------------------------------------------
// launch
// ---------------------------------------------------------------------------
extern "C" void kernel_launch(void* const* d_in, const int* in_sizes, int n_in,
                              void* d_out, int out_size) {
    (void)in_sizes; (void)n_in; (void)out_size;
    const float* x       = (const float*)d_in[0];
    const float* w_pool0 = (const float*)d_in[1];
    const float* b_pool0 = (const float*)d_in[2];
    const float* adj1    = (const float*)d_in[3];
    const float* w_q     = (const float*)d_in[4];
    const float* b_q     = (const float*)d_in[5];
    const float* w_k     = (const float*)d_in[6];
    const float* b_k     = (const float*)d_in[7];
    const float* alpha   = (const float*)d_in[8];
    const float* w_c1    = (const float*)d_in[9];
    const float* b_c1    = (const float*)d_in[10];
    const float* gamma   = (const float*)d_in[11];
    const float* beta    = (const float*)d_in[12];
    const float* w_pool1 = (const float*)d_in[13];
    const float* b_pool1 = (const float*)d_in[14];
    const float* w_cls   = (const float*)d_in[15];
    const float* b_cls   = (const float*)d_in[16];
    float* out = (float*)d_out;

    __half *w0h, *h1, *a1hi, *a1lo;
    float *sbc, *ssbc, *dotb;
    cudaGetSymbolAddress((void**)&w0h,  g_w0h);
    cudaGetSymbolAddress((void**)&h1,   g_h1);
    cudaGetSymbolAddress((void**)&a1hi, g_a1hi);
    cudaGetSymbolAddress((void**)&a1lo, g_a1lo);
    cudaGetSymbolAddress((void**)&sbc,  g_sbc);
    cudaGetSymbolAddress((void**)&ssbc, g_ssbc);
    cudaGetSymbolAddress((void**)&dotb, g_dotb);

    const int smem_bytes = 2 * STG2;   // 139264 (both kernels: 4 tiles)
    cudaFuncSetAttribute(mma_gemm2f, cudaFuncAttributeMaxDynamicSharedMemorySize, smem_bytes);
    cudaFuncSetAttribute(mma_gemm_x, cudaFuncAttributeMaxDynamicSharedMemorySize, smem_bytes);

    // w0 fp16 round + q/k weight means
    k_cvt_w0<<<(unsigned)((long)NJ * TNS / 4 / 256), 256>>>(w_pool0);
    k_wmeans<<<50, 256>>>(w_q, w_k, b_q, b_k);

    // GEMM1 (1-term, BK=128) + fused q/k partials
    mma_gemm_x<<<dim3(NCT, 1, BB), 256, smem_bytes>>>(
        w0h,
        x, (long)PS * TNS,
        TNS, b_pool0,
        h1, (long)NJ * PS, PS);

    // q1/k1 reduce + A1^T build
    k_qkA1<<<dim3(8, BB), 256>>>(adj1, alpha);

    // GEMM2 (1-term, BK=128, inline c1 round) + fused GEMM3 + fused BN-stat/pool
    mma_gemm2f<<<dim3(NCT, 1, BB), 256, smem_bytes>>>(
        w_c1,
        h1, (long)NJ * PS,
        a1hi, a1lo,
        PS, b_c1,
        w_pool1, sbc, ssbc, dotb);

    k_hs4<<<PS / 8, dim3(32, 8)>>>(gamma, beta, w_pool1, b_pool1);
    k_cls<<<BB, 256>>>(w_cls, b_cls, out);
}